// round 1
// baseline (speedup 1.0000x reference)
#include <cuda_runtime.h>
#include <math.h>
#include <stdint.h>

// ---------------------------------------------------------------------------
// Problem constants (shapes fixed by setup_inputs)
// ---------------------------------------------------------------------------
#define B_ 2
#define NV 4
#define H_ 240
#define W_ 240
#define H1_ 120
#define W1_ 120
#define D_ 32
#define NPB 131072            // points per batch (Nr*Np = 2048*64)
#define PT (B_ * NPB)         // 262144 total points
#define INBASE 70             // 2*(D+3)
#define DH 128                // hidden dim
#define TM 128                // point tile per block in MLP kernel
#define LDH 130               // padded activation row stride (bank-conflict free)

// ---------------------------------------------------------------------------
// Scratch (device globals; no dynamic allocation allowed)
// ---------------------------------------------------------------------------
__device__ float g_x[(size_t)PT * INBASE];                    // 70-dim features
__device__ float g_featsT[(size_t)B_ * NV * H1_ * W1_ * D_];  // channel-last feats
__device__ float g_imgsT[(size_t)B_ * NV * H_ * W_ * 3];      // channel-last imgs
__device__ float g_proj[B_ * NV * 12];                        // P = K @ w2c[0:3,:]

// ---------------------------------------------------------------------------
// Kernel 0: per-(b,v) projection matrices  P = K @ inv(c2w)[0:3, :]
// ---------------------------------------------------------------------------
__global__ void proj_kernel(const float* __restrict__ cams) {
    int i = threadIdx.x;
    if (i >= B_ * NV) return;
    const float* c = cams + i * 27;
    float K[9];
#pragma unroll
    for (int j = 0; j < 9; j++) K[j] = c[2 + j];
    float m[16];
#pragma unroll
    for (int j = 0; j < 16; j++) m[j] = c[11 + j];

    float inv[16];
    inv[0]  =  m[5]*m[10]*m[15] - m[5]*m[11]*m[14] - m[9]*m[6]*m[15] + m[9]*m[7]*m[14] + m[13]*m[6]*m[11] - m[13]*m[7]*m[10];
    inv[4]  = -m[4]*m[10]*m[15] + m[4]*m[11]*m[14] + m[8]*m[6]*m[15] - m[8]*m[7]*m[14] - m[12]*m[6]*m[11] + m[12]*m[7]*m[10];
    inv[8]  =  m[4]*m[9]*m[15]  - m[4]*m[11]*m[13] - m[8]*m[5]*m[15] + m[8]*m[7]*m[13] + m[12]*m[5]*m[11] - m[12]*m[7]*m[9];
    inv[12] = -m[4]*m[9]*m[14]  + m[4]*m[10]*m[13] + m[8]*m[5]*m[14] - m[8]*m[6]*m[13] - m[12]*m[5]*m[10] + m[12]*m[6]*m[9];
    inv[1]  = -m[1]*m[10]*m[15] + m[1]*m[11]*m[14] + m[9]*m[2]*m[15] - m[9]*m[3]*m[14] - m[13]*m[2]*m[11] + m[13]*m[3]*m[10];
    inv[5]  =  m[0]*m[10]*m[15] - m[0]*m[11]*m[14] - m[8]*m[2]*m[15] + m[8]*m[3]*m[14] + m[12]*m[2]*m[11] - m[12]*m[3]*m[10];
    inv[9]  = -m[0]*m[9]*m[15]  + m[0]*m[11]*m[13] + m[8]*m[1]*m[15] - m[8]*m[3]*m[13] - m[12]*m[1]*m[11] + m[12]*m[3]*m[9];
    inv[13] =  m[0]*m[9]*m[14]  - m[0]*m[10]*m[13] - m[8]*m[1]*m[14] + m[8]*m[2]*m[13] + m[12]*m[1]*m[10] - m[12]*m[2]*m[9];
    inv[2]  =  m[1]*m[6]*m[15]  - m[1]*m[7]*m[14]  - m[5]*m[2]*m[15] + m[5]*m[3]*m[14] + m[13]*m[2]*m[7]  - m[13]*m[3]*m[6];
    inv[6]  = -m[0]*m[6]*m[15]  + m[0]*m[7]*m[14]  + m[4]*m[2]*m[15] - m[4]*m[3]*m[14] - m[12]*m[2]*m[7]  + m[12]*m[3]*m[6];
    inv[10] =  m[0]*m[5]*m[15]  - m[0]*m[7]*m[13]  - m[4]*m[1]*m[15] + m[4]*m[3]*m[13] + m[12]*m[1]*m[7]  - m[12]*m[3]*m[5];
    inv[14] = -m[0]*m[5]*m[14]  + m[0]*m[6]*m[13]  + m[4]*m[1]*m[14] - m[4]*m[2]*m[13] - m[12]*m[1]*m[6]  + m[12]*m[2]*m[5];
    inv[3]  = -m[1]*m[6]*m[11]  + m[1]*m[7]*m[10]  + m[5]*m[2]*m[11] - m[5]*m[3]*m[10] - m[9]*m[2]*m[7]   + m[9]*m[3]*m[6];
    inv[7]  =  m[0]*m[6]*m[11]  - m[0]*m[7]*m[10]  - m[4]*m[2]*m[11] + m[4]*m[3]*m[10] + m[8]*m[2]*m[7]   - m[8]*m[3]*m[6];
    inv[11] = -m[0]*m[5]*m[11]  + m[0]*m[7]*m[9]   + m[4]*m[1]*m[11] - m[4]*m[3]*m[9]  - m[8]*m[1]*m[7]   + m[8]*m[3]*m[5];
    inv[15] =  m[0]*m[5]*m[10]  - m[0]*m[6]*m[9]   - m[4]*m[1]*m[10] + m[4]*m[2]*m[9]  + m[8]*m[1]*m[6]   - m[8]*m[2]*m[5];

    float det = m[0]*inv[0] + m[1]*inv[4] + m[2]*inv[8] + m[3]*inv[12];
    float id = 1.0f / det;
#pragma unroll
    for (int j = 0; j < 16; j++) inv[j] *= id;

#pragma unroll
    for (int r = 0; r < 3; r++) {
#pragma unroll
        for (int cc = 0; cc < 4; cc++) {
            float s = K[r*3+0]*inv[0*4+cc] + K[r*3+1]*inv[1*4+cc] + K[r*3+2]*inv[2*4+cc];
            g_proj[i*12 + r*4 + cc] = s;
        }
    }
}

// ---------------------------------------------------------------------------
// Transpose feats (B,Nv,D,H1,W1) -> (B,Nv,H1,W1,D)  and imgs similarly
// ---------------------------------------------------------------------------
__global__ void tfeat_kernel(const float* __restrict__ f) {
    int o = blockIdx.x * blockDim.x + threadIdx.x;
    if (o >= B_ * NV * H1_ * W1_ * D_) return;
    int c = o & (D_ - 1);
    int rest = o >> 5;
    int x = rest % W1_;
    int t2 = rest / W1_;
    int y = t2 % H1_;
    int bv = t2 / H1_;
    g_featsT[o] = f[((size_t)(bv * D_ + c)) * (H1_ * W1_) + y * W1_ + x];
}

__global__ void timg_kernel(const float* __restrict__ im) {
    int o = blockIdx.x * blockDim.x + threadIdx.x;
    if (o >= B_ * NV * H_ * W_ * 3) return;
    int c = o % 3;
    int rest = o / 3;
    int x = rest % W_;
    int t2 = rest / W_;
    int y = t2 % H_;
    int bv = t2 / H_;
    g_imgsT[o] = im[((size_t)(bv * 3 + c)) * (H_ * W_) + y * W_ + x];
}

// ---------------------------------------------------------------------------
// Kernel 1: project + bilinear sample + masked mean/var  -> g_x [PT][70]
// ---------------------------------------------------------------------------
__global__ void __launch_bounds__(256) featurize_kernel(const float* __restrict__ xyz) {
    int gp = blockIdx.x * blockDim.x + threadIdx.x;
    if (gp >= PT) return;
    int b = gp / NPB;

    float X = xyz[(size_t)gp * 3 + 0];
    float Y = xyz[(size_t)gp * 3 + 1];
    float Z = xyz[(size_t)gp * 3 + 2];

    float sum[35], sq[35];
#pragma unroll
    for (int i = 0; i < 35; i++) { sum[i] = 0.f; sq[i] = 0.f; }
    float s = 0.f;

    const float SX = (float)(W1_ - 1) / (float)(W_ - 1);
    const float SY = (float)(H1_ - 1) / (float)(H_ - 1);

    for (int v = 0; v < NV; v++) {
        const float* Pm = &g_proj[(b * NV + v) * 12];
        float pxn = Pm[0]*X + Pm[1]*Y + Pm[2]*Z  + Pm[3];
        float pyn = Pm[4]*X + Pm[5]*Y + Pm[6]*Z  + Pm[7];
        float pz  = Pm[8]*X + Pm[9]*Y + Pm[10]*Z + Pm[11];
        float d = fmaxf(pz, 1e-8f);
        float px = pxn / d;
        float py = pyn / d;
        bool inb = (pz > 1e-4f) && (px >= 0.f) && (px <= (float)(W_ - 1))
                                && (py >= 0.f) && (py <= (float)(H_ - 1));
        if (!inb) continue;
        s += 1.f;

        // --- image bilinear (3 ch, channel-last) ---
        {
            float x0f = floorf(px), y0f = floorf(py);
            float wx = px - x0f, wy = py - y0f;
            int x0 = (int)x0f;
            int y0 = (int)y0f;
            int x1 = min(x0 + 1, W_ - 1);
            int y1 = min(y0 + 1, H_ - 1);
            float w00 = (1.f - wx) * (1.f - wy);
            float w01 = wx * (1.f - wy);
            float w10 = (1.f - wx) * wy;
            float w11 = wx * wy;
            const float* ib = g_imgsT + (size_t)(b * NV + v) * H_ * W_ * 3;
            const float* p00 = ib + (size_t)(y0 * W_ + x0) * 3;
            const float* p01 = ib + (size_t)(y0 * W_ + x1) * 3;
            const float* p10 = ib + (size_t)(y1 * W_ + x0) * 3;
            const float* p11 = ib + (size_t)(y1 * W_ + x1) * 3;
#pragma unroll
            for (int c = 0; c < 3; c++) {
                float val = p00[c]*w00 + p01[c]*w01 + p10[c]*w10 + p11[c]*w11;
                sum[c] += val;
                sq[c]  += val * val;
            }
        }

        // --- feature bilinear (32 ch, channel-last, float4 taps) ---
        {
            float fx = px * SX;
            float fy = py * SY;
            float x0f = floorf(fx), y0f = floorf(fy);
            float wx = fx - x0f, wy = fy - y0f;
            int x0 = (int)x0f;
            int y0 = (int)y0f;
            int x1 = min(x0 + 1, W1_ - 1);
            int y1 = min(y0 + 1, H1_ - 1);
            float w00 = (1.f - wx) * (1.f - wy);
            float w01 = wx * (1.f - wy);
            float w10 = (1.f - wx) * wy;
            float w11 = wx * wy;
            const float* fb = g_featsT + (size_t)(b * NV + v) * H1_ * W1_ * D_;
            const float4* t00 = reinterpret_cast<const float4*>(fb + (size_t)(y0 * W1_ + x0) * D_);
            const float4* t01 = reinterpret_cast<const float4*>(fb + (size_t)(y0 * W1_ + x1) * D_);
            const float4* t10 = reinterpret_cast<const float4*>(fb + (size_t)(y1 * W1_ + x0) * D_);
            const float4* t11 = reinterpret_cast<const float4*>(fb + (size_t)(y1 * W1_ + x1) * D_);
#pragma unroll
            for (int q = 0; q < 8; q++) {
                float4 a = t00[q], bb = t01[q], cc = t10[q], dd = t11[q];
                float v0 = a.x*w00 + bb.x*w01 + cc.x*w10 + dd.x*w11;
                float v1 = a.y*w00 + bb.y*w01 + cc.y*w10 + dd.y*w11;
                float v2 = a.z*w00 + bb.z*w01 + cc.z*w10 + dd.z*w11;
                float v3 = a.w*w00 + bb.w*w01 + cc.w*w10 + dd.w*w11;
                int o = 3 + q * 4;
                sum[o+0] += v0; sq[o+0] += v0 * v0;
                sum[o+1] += v1; sq[o+1] += v1 * v1;
                sum[o+2] += v2; sq[o+2] += v2 * v2;
                sum[o+3] += v3; sq[o+3] += v3 * v3;
            }
        }
    }

    float denom = s + 1e-6f;
    float invd = 1.f / denom;
    float alpha = s * invd;
    float* xo = g_x + (size_t)gp * INBASE;
#pragma unroll
    for (int i = 0; i < 35; i++) {
        float m  = sum[i] * invd;
        float e2 = sq[i] * invd;
        xo[i]      = m;
        xo[35 + i] = e2 - (2.f - alpha) * m * m;   // exact algebra of sum w (f-m)^2
    }
}

// ---------------------------------------------------------------------------
// Kernel 2: fused MLP chain (70->128, 4x 128->128 leaky, heads)
// Block: 256 threads, tile TM=128 points. 8x8 register micro-tiles.
// ---------------------------------------------------------------------------
template <int KK>
__device__ __forceinline__ void gemm_tile(const float* __restrict__ h,
                                          const float* __restrict__ ws,
                                          float (&acc)[8][8], int ty, int tx) {
#pragma unroll
    for (int i = 0; i < 8; i++)
#pragma unroll
        for (int j = 0; j < 8; j++) acc[i][j] = 0.f;

#pragma unroll 4
    for (int k = 0; k < KK; k++) {
        float a[8];
#pragma unroll
        for (int i = 0; i < 8; i++) a[i] = h[(ty * 8 + i) * LDH + k];
        float4 b0 = *reinterpret_cast<const float4*>(ws + k * DH + tx * 8);
        float4 b1 = *reinterpret_cast<const float4*>(ws + k * DH + tx * 8 + 4);
        float bj[8] = {b0.x, b0.y, b0.z, b0.w, b1.x, b1.y, b1.z, b1.w};
#pragma unroll
        for (int i = 0; i < 8; i++)
#pragma unroll
            for (int j = 0; j < 8; j++)
                acc[i][j] = fmaf(a[i], bj[j], acc[i][j]);
    }
}

__device__ __forceinline__ void write_tile(float* __restrict__ h,
                                           const float* __restrict__ bs,
                                           float (&acc)[8][8], int ty, int tx,
                                           bool leaky) {
#pragma unroll
    for (int i = 0; i < 8; i++) {
        int r = ty * 8 + i;
#pragma unroll
        for (int j = 0; j < 8; j++) {
            float v = acc[i][j] + bs[tx * 8 + j];
            if (leaky) v = v > 0.f ? v : 0.01f * v;
            h[r * LDH + tx * 8 + j] = v;
        }
    }
}

__global__ void __launch_bounds__(256) mlp_kernel(
    const float* __restrict__ w0, const float* __restrict__ b0,
    const float* __restrict__ w1, const float* __restrict__ b1,
    const float* __restrict__ w2, const float* __restrict__ b2,
    const float* __restrict__ w3, const float* __restrict__ b3,
    const float* __restrict__ w4, const float* __restrict__ b4,
    const float* __restrict__ w5, const float* __restrict__ b5,
    const float* __restrict__ dw, const float* __restrict__ db,
    float* __restrict__ out) {

    extern __shared__ float sm[];
    float* h    = sm;                    // TM * LDH
    float* ws   = h + TM * LDH;          // DH * DH
    float* bs   = ws + DH * DH;          // DH
    float* w5s  = bs + DH;               // DH * 3
    float* dws  = w5s + DH * 3;          // DH

    int tid = threadIdx.x;
    int p0 = blockIdx.x * TM;
    int tx = tid & 15;
    int ty = tid >> 4;

    // load x tile (128 x 70)
    for (int i = tid; i < TM * INBASE; i += 256) {
        int r = i / INBASE, c = i % INBASE;
        h[r * LDH + c] = g_x[(size_t)(p0 + r) * INBASE + c];
    }
    // load W0 (70x128), b0, head weights
    for (int i = tid; i < INBASE * DH; i += 256) ws[i] = w0[i];
    for (int i = tid; i < DH * 3; i += 256) w5s[i] = w5[i];
    if (tid < DH) { bs[tid] = b0[tid]; dws[tid] = dw[tid]; }
    __syncthreads();

    float acc[8][8];

    // layer 0: x @ W0 + b0  (no activation) -> pf
    gemm_tile<INBASE>(h, ws, acc, ty, tx);
    __syncthreads();
    write_tile(h, bs, acc, ty, tx, false);
    __syncthreads();

    // sigma head from pf (while pf still in smem)
    if (tid < TM) {
        float sacc = db[0];
#pragma unroll 4
        for (int k = 0; k < DH; k++) sacc = fmaf(h[tid * LDH + k], dws[k], sacc);
        out[(size_t)(p0 + tid) * 4 + 3] = fmaxf(sacc, 0.f);
    }

    // layers 1..4 (128->128, leaky relu 0.01)
    const float* Wl[4] = {w1, w2, w3, w4};
    const float* Bl[4] = {b1, b2, b3, b4};
    for (int l = 0; l < 4; l++) {
        for (int i = tid; i < DH * DH; i += 256) ws[i] = Wl[l][i];
        if (tid < DH) bs[tid] = Bl[l][tid];
        __syncthreads();
        gemm_tile<DH>(h, ws, acc, ty, tx);
        __syncthreads();
        write_tile(h, bs, acc, ty, tx, true);
        __syncthreads();
    }

    // rgb head: tanh(h @ w5 + b5)
    if (tid < TM) {
        float r0 = b5[0], r1 = b5[1], r2 = b5[2];
#pragma unroll 4
        for (int k = 0; k < DH; k++) {
            float hv = h[tid * LDH + k];
            r0 = fmaf(hv, w5s[k * 3 + 0], r0);
            r1 = fmaf(hv, w5s[k * 3 + 1], r1);
            r2 = fmaf(hv, w5s[k * 3 + 2], r2);
        }
        size_t o = (size_t)(p0 + tid) * 4;
        out[o + 0] = tanhf(r0);
        out[o + 1] = tanhf(r1);
        out[o + 2] = tanhf(r2);
    }
}

// ---------------------------------------------------------------------------
// Launch
// ---------------------------------------------------------------------------
extern "C" void kernel_launch(void* const* d_in, const int* in_sizes, int n_in,
                              void* d_out, int out_size) {
    const float* xyz       = (const float*)d_in[0];
    // d_in[1] = cam (unused by reference)
    const float* src_imgs  = (const float*)d_in[2];
    const float* src_cams  = (const float*)d_in[3];
    const float* src_feats = (const float*)d_in[4];
    const float* w0 = (const float*)d_in[5];
    const float* b0 = (const float*)d_in[6];
    const float* w1 = (const float*)d_in[7];
    const float* b1 = (const float*)d_in[8];
    const float* w2 = (const float*)d_in[9];
    const float* b2 = (const float*)d_in[10];
    const float* w3 = (const float*)d_in[11];
    const float* b3 = (const float*)d_in[12];
    const float* w4 = (const float*)d_in[13];
    const float* b4 = (const float*)d_in[14];
    const float* w5 = (const float*)d_in[15];
    const float* b5 = (const float*)d_in[16];
    const float* dw = (const float*)d_in[17];
    const float* db = (const float*)d_in[18];
    float* out = (float*)d_out;

    const int smem_bytes = (TM * LDH + DH * DH + DH + DH * 3 + DH) * (int)sizeof(float);
    cudaFuncSetAttribute(mlp_kernel, cudaFuncAttributeMaxDynamicSharedMemorySize, smem_bytes);

    proj_kernel<<<1, 32>>>(src_cams);
    tfeat_kernel<<<(B_ * NV * H1_ * W1_ * D_) / 256, 256>>>(src_feats);
    timg_kernel<<<(B_ * NV * H_ * W_ * 3 + 255) / 256, 256>>>(src_imgs);
    featurize_kernel<<<PT / 256, 256>>>(xyz);
    mlp_kernel<<<PT / TM, 256, smem_bytes>>>(w0, b0, w1, b1, w2, b2, w3, b3,
                                             w4, b4, w5, b5, dw, db, out);
}

// round 3
// speedup vs baseline: 1.5706x; 1.5706x over previous
#include <cuda_runtime.h>
#include <math.h>
#include <stdint.h>

// ---------------------------------------------------------------------------
// Problem constants (shapes fixed by setup_inputs)
// ---------------------------------------------------------------------------
#define B_ 2
#define NV 4
#define H_ 240
#define W_ 240
#define H1_ 120
#define W1_ 120
#define D_ 32
#define NPB 131072            // points per batch (Nr*Np = 2048*64)
#define PT (B_ * NPB)         // 262144 total points
#define INBASE 70             // 2*(D+3)
#define DH 128                // hidden dim
#define TM 128                // point tile per block in MLP kernel

#define ACT_STRIDE 132        // 132 % 32 == 4  -> A-frag LDS conflict-free
#define WS_STRIDE  136        // 136 % 32 == 8  -> B-frag LDS conflict-free

// ---------------------------------------------------------------------------
// Scratch (device globals; no dynamic allocation allowed)
// ---------------------------------------------------------------------------
__device__ float g_x[(size_t)PT * INBASE];                    // 70-dim features
__device__ float g_featsT[(size_t)B_ * NV * H1_ * W1_ * D_];  // channel-last feats
__device__ float g_imgsT[(size_t)B_ * NV * H_ * W_ * 3];      // channel-last imgs
__device__ float g_proj[B_ * NV * 12];                        // P = K @ w2c[0:3,:]

// ---------------------------------------------------------------------------
// Kernel 0: per-(b,v) projection matrices  P = K @ inv(c2w)[0:3, :]
// ---------------------------------------------------------------------------
__global__ void proj_kernel(const float* __restrict__ cams) {
    int i = threadIdx.x;
    if (i >= B_ * NV) return;
    const float* c = cams + i * 27;
    float K[9];
#pragma unroll
    for (int j = 0; j < 9; j++) K[j] = c[2 + j];
    float m[16];
#pragma unroll
    for (int j = 0; j < 16; j++) m[j] = c[11 + j];

    float inv[16];
    inv[0]  =  m[5]*m[10]*m[15] - m[5]*m[11]*m[14] - m[9]*m[6]*m[15] + m[9]*m[7]*m[14] + m[13]*m[6]*m[11] - m[13]*m[7]*m[10];
    inv[4]  = -m[4]*m[10]*m[15] + m[4]*m[11]*m[14] + m[8]*m[6]*m[15] - m[8]*m[7]*m[14] - m[12]*m[6]*m[11] + m[12]*m[7]*m[10];
    inv[8]  =  m[4]*m[9]*m[15]  - m[4]*m[11]*m[13] - m[8]*m[5]*m[15] + m[8]*m[7]*m[13] + m[12]*m[5]*m[11] - m[12]*m[7]*m[9];
    inv[12] = -m[4]*m[9]*m[14]  + m[4]*m[10]*m[13] + m[8]*m[5]*m[14] - m[8]*m[6]*m[13] - m[12]*m[5]*m[10] + m[12]*m[6]*m[9];
    inv[1]  = -m[1]*m[10]*m[15] + m[1]*m[11]*m[14] + m[9]*m[2]*m[15] - m[9]*m[3]*m[14] - m[13]*m[2]*m[11] + m[13]*m[3]*m[10];
    inv[5]  =  m[0]*m[10]*m[15] - m[0]*m[11]*m[14] - m[8]*m[2]*m[15] + m[8]*m[3]*m[14] + m[12]*m[2]*m[11] - m[12]*m[3]*m[10];
    inv[9]  = -m[0]*m[9]*m[15]  + m[0]*m[11]*m[13] + m[8]*m[1]*m[15] - m[8]*m[3]*m[13] - m[12]*m[1]*m[11] + m[12]*m[3]*m[9];
    inv[13] =  m[0]*m[9]*m[14]  - m[0]*m[10]*m[13] - m[8]*m[1]*m[14] + m[8]*m[2]*m[13] + m[12]*m[1]*m[10] - m[12]*m[2]*m[9];
    inv[2]  =  m[1]*m[6]*m[15]  - m[1]*m[7]*m[14]  - m[5]*m[2]*m[15] + m[5]*m[3]*m[14] + m[13]*m[2]*m[7]  - m[13]*m[3]*m[6];
    inv[6]  = -m[0]*m[6]*m[15]  + m[0]*m[7]*m[14]  + m[4]*m[2]*m[15] - m[4]*m[3]*m[14] - m[12]*m[2]*m[7]  + m[12]*m[3]*m[6];
    inv[10] =  m[0]*m[5]*m[15]  - m[0]*m[7]*m[13]  - m[4]*m[1]*m[15] + m[4]*m[3]*m[13] + m[12]*m[1]*m[7]  - m[12]*m[3]*m[5];
    inv[14] = -m[0]*m[5]*m[14]  + m[0]*m[6]*m[13]  + m[4]*m[1]*m[14] - m[4]*m[2]*m[13] - m[12]*m[1]*m[6]  + m[12]*m[2]*m[5];
    inv[3]  = -m[1]*m[6]*m[11]  + m[1]*m[7]*m[10]  + m[5]*m[2]*m[11] - m[5]*m[3]*m[10] - m[9]*m[2]*m[7]   + m[9]*m[3]*m[6];
    inv[7]  =  m[0]*m[6]*m[11]  - m[0]*m[7]*m[10]  - m[4]*m[2]*m[11] + m[4]*m[3]*m[10] + m[8]*m[2]*m[7]   - m[8]*m[3]*m[6];
    inv[11] = -m[0]*m[5]*m[11]  + m[0]*m[7]*m[9]   + m[4]*m[1]*m[11] - m[4]*m[3]*m[9]  - m[8]*m[1]*m[7]   + m[8]*m[3]*m[5];
    inv[15] =  m[0]*m[5]*m[10]  - m[0]*m[6]*m[9]   - m[4]*m[1]*m[10] + m[4]*m[2]*m[9]  + m[8]*m[1]*m[6]   - m[8]*m[2]*m[5];

    float det = m[0]*inv[0] + m[1]*inv[4] + m[2]*inv[8] + m[3]*inv[12];
    float id = 1.0f / det;
#pragma unroll
    for (int j = 0; j < 16; j++) inv[j] *= id;

#pragma unroll
    for (int r = 0; r < 3; r++) {
#pragma unroll
        for (int cc = 0; cc < 4; cc++) {
            float s = K[r*3+0]*inv[0*4+cc] + K[r*3+1]*inv[1*4+cc] + K[r*3+2]*inv[2*4+cc];
            g_proj[i*12 + r*4 + cc] = s;
        }
    }
}

// ---------------------------------------------------------------------------
// Transpose feats (B,Nv,D,H1,W1) -> (B,Nv,H1,W1,D)  and imgs similarly
// ---------------------------------------------------------------------------
__global__ void tfeat_kernel(const float* __restrict__ f) {
    int o = blockIdx.x * blockDim.x + threadIdx.x;
    if (o >= B_ * NV * H1_ * W1_ * D_) return;
    int c = o & (D_ - 1);
    int rest = o >> 5;
    int x = rest % W1_;
    int t2 = rest / W1_;
    int y = t2 % H1_;
    int bv = t2 / H1_;
    g_featsT[o] = f[((size_t)(bv * D_ + c)) * (H1_ * W1_) + y * W1_ + x];
}

__global__ void timg_kernel(const float* __restrict__ im) {
    int o = blockIdx.x * blockDim.x + threadIdx.x;
    if (o >= B_ * NV * H_ * W_ * 3) return;
    int c = o % 3;
    int rest = o / 3;
    int x = rest % W_;
    int t2 = rest / W_;
    int y = t2 % H_;
    int bv = t2 / H_;
    g_imgsT[o] = im[((size_t)(bv * 3 + c)) * (H_ * W_) + y * W_ + x];
}

// ---------------------------------------------------------------------------
// Kernel 1: project + bilinear sample + masked mean/var  -> g_x [PT][70]
// ---------------------------------------------------------------------------
__global__ void __launch_bounds__(256) featurize_kernel(const float* __restrict__ xyz) {
    int gp = blockIdx.x * blockDim.x + threadIdx.x;
    if (gp >= PT) return;
    int b = gp / NPB;

    float X = xyz[(size_t)gp * 3 + 0];
    float Y = xyz[(size_t)gp * 3 + 1];
    float Z = xyz[(size_t)gp * 3 + 2];

    float sum[35], sq[35];
#pragma unroll
    for (int i = 0; i < 35; i++) { sum[i] = 0.f; sq[i] = 0.f; }
    float s = 0.f;

    const float SX = (float)(W1_ - 1) / (float)(W_ - 1);
    const float SY = (float)(H1_ - 1) / (float)(H_ - 1);

    for (int v = 0; v < NV; v++) {
        const float* Pm = &g_proj[(b * NV + v) * 12];
        float pxn = Pm[0]*X + Pm[1]*Y + Pm[2]*Z  + Pm[3];
        float pyn = Pm[4]*X + Pm[5]*Y + Pm[6]*Z  + Pm[7];
        float pz  = Pm[8]*X + Pm[9]*Y + Pm[10]*Z + Pm[11];
        float d = fmaxf(pz, 1e-8f);
        float px = pxn / d;
        float py = pyn / d;
        bool inb = (pz > 1e-4f) && (px >= 0.f) && (px <= (float)(W_ - 1))
                                && (py >= 0.f) && (py <= (float)(H_ - 1));
        if (!inb) continue;
        s += 1.f;

        // --- image bilinear (3 ch, channel-last) ---
        {
            float x0f = floorf(px), y0f = floorf(py);
            float wx = px - x0f, wy = py - y0f;
            int x0 = (int)x0f;
            int y0 = (int)y0f;
            int x1 = min(x0 + 1, W_ - 1);
            int y1 = min(y0 + 1, H_ - 1);
            float w00 = (1.f - wx) * (1.f - wy);
            float w01 = wx * (1.f - wy);
            float w10 = (1.f - wx) * wy;
            float w11 = wx * wy;
            const float* ib = g_imgsT + (size_t)(b * NV + v) * H_ * W_ * 3;
            const float* p00 = ib + (size_t)(y0 * W_ + x0) * 3;
            const float* p01 = ib + (size_t)(y0 * W_ + x1) * 3;
            const float* p10 = ib + (size_t)(y1 * W_ + x0) * 3;
            const float* p11 = ib + (size_t)(y1 * W_ + x1) * 3;
#pragma unroll
            for (int c = 0; c < 3; c++) {
                float val = p00[c]*w00 + p01[c]*w01 + p10[c]*w10 + p11[c]*w11;
                sum[c] += val;
                sq[c]  += val * val;
            }
        }

        // --- feature bilinear (32 ch, channel-last, float4 taps) ---
        {
            float fx = px * SX;
            float fy = py * SY;
            float x0f = floorf(fx), y0f = floorf(fy);
            float wx = fx - x0f, wy = fy - y0f;
            int x0 = (int)x0f;
            int y0 = (int)y0f;
            int x1 = min(x0 + 1, W1_ - 1);
            int y1 = min(y0 + 1, H1_ - 1);
            float w00 = (1.f - wx) * (1.f - wy);
            float w01 = wx * (1.f - wy);
            float w10 = (1.f - wx) * wy;
            float w11 = wx * wy;
            const float* fb = g_featsT + (size_t)(b * NV + v) * H1_ * W1_ * D_;
            const float4* t00 = reinterpret_cast<const float4*>(fb + (size_t)(y0 * W1_ + x0) * D_);
            const float4* t01 = reinterpret_cast<const float4*>(fb + (size_t)(y0 * W1_ + x1) * D_);
            const float4* t10 = reinterpret_cast<const float4*>(fb + (size_t)(y1 * W1_ + x0) * D_);
            const float4* t11 = reinterpret_cast<const float4*>(fb + (size_t)(y1 * W1_ + x1) * D_);
#pragma unroll
            for (int q = 0; q < 8; q++) {
                float4 a = t00[q], bb = t01[q], cc = t10[q], dd = t11[q];
                float v0 = a.x*w00 + bb.x*w01 + cc.x*w10 + dd.x*w11;
                float v1 = a.y*w00 + bb.y*w01 + cc.y*w10 + dd.y*w11;
                float v2 = a.z*w00 + bb.z*w01 + cc.z*w10 + dd.z*w11;
                float v3 = a.w*w00 + bb.w*w01 + cc.w*w10 + dd.w*w11;
                int o = 3 + q * 4;
                sum[o+0] += v0; sq[o+0] += v0 * v0;
                sum[o+1] += v1; sq[o+1] += v1 * v1;
                sum[o+2] += v2; sq[o+2] += v2 * v2;
                sum[o+3] += v3; sq[o+3] += v3 * v3;
            }
        }
    }

    float denom = s + 1e-6f;
    float invd = 1.f / denom;
    float alpha = s * invd;
    float* xo = g_x + (size_t)gp * INBASE;
#pragma unroll
    for (int i = 0; i < 35; i++) {
        float m  = sum[i] * invd;
        float e2 = sq[i] * invd;
        xo[i]      = m;
        xo[35 + i] = e2 - (2.f - alpha) * m * m;   // exact algebra of sum w (f-m)^2
    }
}

// ---------------------------------------------------------------------------
// tf32 helpers
// ---------------------------------------------------------------------------
__device__ __forceinline__ float to_tf32(float x) {
    uint32_t r;
    asm("cvt.rna.tf32.f32 %0, %1;" : "=r"(r) : "f"(x));
    return __uint_as_float(r);
}

__device__ __forceinline__ void mma_tf32(float (&d)[4], const uint32_t (&a)[4],
                                         const uint32_t (&b)[2]) {
    asm volatile(
        "mma.sync.aligned.m16n8k8.row.col.f32.tf32.tf32.f32 "
        "{%0,%1,%2,%3}, {%4,%5,%6,%7}, {%8,%9}, {%0,%1,%2,%3};"
        : "+f"(d[0]), "+f"(d[1]), "+f"(d[2]), "+f"(d[3])
        : "r"(a[0]), "r"(a[1]), "r"(a[2]), "r"(a[3]), "r"(b[0]), "r"(b[1]));
}

// ---------------------------------------------------------------------------
// Kernel 2: fused MLP chain on tensor cores (tf32 mma.m16n8k8)
// Block: 256 threads (8 warps), tile 128 points.
// Warp (m_blk = warp&3, n_blk = warp>>2) owns a 32x64 output tile.
// ---------------------------------------------------------------------------
template <int KSTEPS>
__device__ __forceinline__ void mma_gemm(const float* __restrict__ act,
                                         const float* __restrict__ ws,
                                         float (&acc)[2][8][4],
                                         int lane, int m_blk, int n_blk) {
#pragma unroll
    for (int mi = 0; mi < 2; mi++)
#pragma unroll
        for (int ni = 0; ni < 8; ni++)
#pragma unroll
            for (int j = 0; j < 4; j++) acc[mi][ni][j] = 0.f;

    const int r = lane >> 2;
    const int c = lane & 3;

#pragma unroll
    for (int kt = 0; kt < KSTEPS; kt++) {
        const int k0 = kt * 8;
        uint32_t a[2][4];
#pragma unroll
        for (int mi = 0; mi < 2; mi++) {
            const float* ab = act + (m_blk * 32 + mi * 16) * ACT_STRIDE + k0;
            a[mi][0] = __float_as_uint(ab[r * ACT_STRIDE + c]);
            a[mi][1] = __float_as_uint(ab[(r + 8) * ACT_STRIDE + c]);
            a[mi][2] = __float_as_uint(ab[r * ACT_STRIDE + c + 4]);
            a[mi][3] = __float_as_uint(ab[(r + 8) * ACT_STRIDE + c + 4]);
        }
        uint32_t bfr[8][2];
#pragma unroll
        for (int ni = 0; ni < 8; ni++) {
            const float* bb = ws + (k0 + c) * WS_STRIDE + n_blk * 64 + ni * 8 + r;
            bfr[ni][0] = __float_as_uint(bb[0]);
            bfr[ni][1] = __float_as_uint(bb[4 * WS_STRIDE]);
        }
#pragma unroll
        for (int mi = 0; mi < 2; mi++)
#pragma unroll
            for (int ni = 0; ni < 8; ni++)
                mma_tf32(acc[mi][ni], a[mi], bfr[ni]);
    }
}

__device__ __forceinline__ void epilogue(float* __restrict__ act,
                                         const float* __restrict__ bs,
                                         float (&acc)[2][8][4],
                                         int lane, int m_blk, int n_blk,
                                         bool leaky) {
    const int r = lane >> 2;
    const int c2 = (lane & 3) * 2;
#pragma unroll
    for (int mi = 0; mi < 2; mi++) {
        const int row0 = m_blk * 32 + mi * 16 + r;
#pragma unroll
        for (int ni = 0; ni < 8; ni++) {
            const int col = n_blk * 64 + ni * 8 + c2;
            float v0 = acc[mi][ni][0] + bs[col];
            float v1 = acc[mi][ni][1] + bs[col + 1];
            float v2 = acc[mi][ni][2] + bs[col];
            float v3 = acc[mi][ni][3] + bs[col + 1];
            if (leaky) {
                v0 = v0 > 0.f ? v0 : 0.01f * v0;
                v1 = v1 > 0.f ? v1 : 0.01f * v1;
                v2 = v2 > 0.f ? v2 : 0.01f * v2;
                v3 = v3 > 0.f ? v3 : 0.01f * v3;
            }
            act[row0 * ACT_STRIDE + col]           = to_tf32(v0);
            act[row0 * ACT_STRIDE + col + 1]       = to_tf32(v1);
            act[(row0 + 8) * ACT_STRIDE + col]     = to_tf32(v2);
            act[(row0 + 8) * ACT_STRIDE + col + 1] = to_tf32(v3);
        }
    }
}

__global__ void __launch_bounds__(256) mlp_mma_kernel(
    const float* __restrict__ w0, const float* __restrict__ b0,
    const float* __restrict__ w1, const float* __restrict__ b1,
    const float* __restrict__ w2, const float* __restrict__ b2,
    const float* __restrict__ w3, const float* __restrict__ b3,
    const float* __restrict__ w4, const float* __restrict__ b4,
    const float* __restrict__ w5, const float* __restrict__ b5,
    const float* __restrict__ dw, const float* __restrict__ db,
    float* __restrict__ out) {

    extern __shared__ float sm[];
    float* act = sm;                          // 128 * ACT_STRIDE
    float* ws  = act + 128 * ACT_STRIDE;      // 128 * WS_STRIDE
    float* bs  = ws + 128 * WS_STRIDE;        // 128
    float* dws = bs + 128;                    // 128
    float* w5s = dws + 128;                   // 384

    const int tid  = threadIdx.x;
    const int lane = tid & 31;
    const int warp = tid >> 5;
    const int m_blk = warp & 3;
    const int n_blk = warp >> 2;
    const int p0 = blockIdx.x * TM;

    // stage x tile (128 x 70 -> padded 72), convert to tf32
    for (int i = tid; i < TM * 72; i += 256) {
        int r = i / 72, c = i % 72;
        float v = (c < INBASE) ? g_x[(size_t)(p0 + r) * INBASE + c] : 0.f;
        act[r * ACT_STRIDE + c] = to_tf32(v);
    }
    // stage W0 (70x128 -> padded 72 rows), b0, head weights
    for (int i = tid; i < 72 * DH; i += 256) {
        int k = i >> 7, n = i & 127;
        float v = (k < INBASE) ? w0[i] : 0.f;
        ws[k * WS_STRIDE + n] = to_tf32(v);
    }
    if (tid < DH) { bs[tid] = b0[tid]; dws[tid] = dw[tid]; }
    for (int i = tid; i < DH * 3; i += 256) w5s[i] = w5[i];
    __syncthreads();

    float acc[2][8][4];

    // ---- layer 0: x @ W0 + b0 (no activation) -> pf ----
    mma_gemm<9>(act, ws, acc, lane, m_blk, n_blk);
    __syncthreads();
    epilogue(act, bs, acc, lane, m_blk, n_blk, false);
    // stage W1
    for (int i = tid; i < DH * DH; i += 256)
        ws[(i >> 7) * WS_STRIDE + (i & 127)] = to_tf32(w1[i]);
    if (tid < DH) bs[tid] = b1[tid];
    __syncthreads();

    // ---- sigma head: relu(pf @ dw + db), skewed-k conflict-free dot ----
    if (tid < TM) {
        float sacc = db[0];
#pragma unroll 4
        for (int kk = 0; kk < DH; kk++) {
            int k = (kk + lane) & (DH - 1);
            sacc = fmaf(act[tid * ACT_STRIDE + k], dws[k], sacc);
        }
        out[(size_t)(p0 + tid) * 4 + 3] = fmaxf(sacc, 0.f);
    }

    // ---- layers 1..4 (128->128, leaky 0.01) ----
    const float* Wl[4] = {w1, w2, w3, w4};
    const float* Bl[4] = {b1, b2, b3, b4};
#pragma unroll 1
    for (int l = 0; l < 4; l++) {
        mma_gemm<16>(act, ws, acc, lane, m_blk, n_blk);
        __syncthreads();
        epilogue(act, bs, acc, lane, m_blk, n_blk, true);
        if (l < 3) {
            for (int i = tid; i < DH * DH; i += 256)
                ws[(i >> 7) * WS_STRIDE + (i & 127)] = to_tf32(Wl[l + 1][i]);
            if (tid < DH) bs[tid] = Bl[l + 1][tid];
        }
        __syncthreads();
    }

    // ---- rgb head: tanh(h4 @ w5 + b5), skewed-k ----
    if (tid < TM) {
        float r0 = b5[0], r1 = b5[1], r2 = b5[2];
#pragma unroll 4
        for (int kk = 0; kk < DH; kk++) {
            int k = (kk + lane) & (DH - 1);
            float hv = act[tid * ACT_STRIDE + k];
            r0 = fmaf(hv, w5s[k * 3 + 0], r0);
            r1 = fmaf(hv, w5s[k * 3 + 1], r1);
            r2 = fmaf(hv, w5s[k * 3 + 2], r2);
        }
        size_t o = (size_t)(p0 + tid) * 4;
        out[o + 0] = tanhf(r0);
        out[o + 1] = tanhf(r1);
        out[o + 2] = tanhf(r2);
    }
}

// ---------------------------------------------------------------------------
// Launch
// ---------------------------------------------------------------------------
extern "C" void kernel_launch(void* const* d_in, const int* in_sizes, int n_in,
                              void* d_out, int out_size) {
    const float* xyz       = (const float*)d_in[0];
    // d_in[1] = cam (unused by reference)
    const float* src_imgs  = (const float*)d_in[2];
    const float* src_cams  = (const float*)d_in[3];
    const float* src_feats = (const float*)d_in[4];
    const float* w0 = (const float*)d_in[5];
    const float* b0 = (const float*)d_in[6];
    const float* w1 = (const float*)d_in[7];
    const float* b1 = (const float*)d_in[8];
    const float* w2 = (const float*)d_in[9];
    const float* b2 = (const float*)d_in[10];
    const float* w3 = (const float*)d_in[11];
    const float* b3 = (const float*)d_in[12];
    const float* w4 = (const float*)d_in[13];
    const float* b4 = (const float*)d_in[14];
    const float* w5 = (const float*)d_in[15];
    const float* b5 = (const float*)d_in[16];
    const float* dw = (const float*)d_in[17];
    const float* db = (const float*)d_in[18];
    float* out = (float*)d_out;

    const int smem_bytes =
        (128 * ACT_STRIDE + 128 * WS_STRIDE + 128 + 128 + 384) * (int)sizeof(float);
    static int attr_set = 0;
    if (!attr_set) {
        cudaFuncSetAttribute(mlp_mma_kernel,
                             cudaFuncAttributeMaxDynamicSharedMemorySize, smem_bytes);
        attr_set = 1;
    }

    proj_kernel<<<1, 32>>>(src_cams);
    tfeat_kernel<<<(B_ * NV * H1_ * W1_ * D_) / 256, 256>>>(src_feats);
    timg_kernel<<<(B_ * NV * H_ * W_ * 3 + 255) / 256, 256>>>(src_imgs);
    featurize_kernel<<<PT / 256, 256>>>(xyz);
    mlp_mma_kernel<<<PT / TM, 256, smem_bytes>>>(w0, b0, w1, b1, w2, b2, w3, b3,
                                                 w4, b4, w5, b5, dw, db, out);
}

// round 4
// speedup vs baseline: 3.2117x; 2.0449x over previous
#include <cuda_runtime.h>
#include <math.h>
#include <stdint.h>

// ---------------------------------------------------------------------------
// Problem constants (shapes fixed by setup_inputs)
// ---------------------------------------------------------------------------
#define B_ 2
#define NV 4
#define H_ 240
#define W_ 240
#define H1_ 120
#define W1_ 120
#define D_ 32
#define NPB 131072            // points per batch (Nr*Np = 2048*64)
#define PT (B_ * NPB)         // 262144 total points
#define INBASE 70             // 2*(D+3)
#define XPAD 72               // padded feature row (16B-aligned rows for cp.async)
#define DH 128                // hidden dim
#define TM 128                // point tile per block in MLP kernel
#define MLP_THREADS 512

#define ACT_STRIDE 132        // 132 % 32 == 4  -> A-frag LDS conflict-free, 528B row (16B mult)
#define WS_STRIDE  136        // 136 % 32 == 8  -> B-frag LDS conflict-free, 544B row (16B mult)

// ---------------------------------------------------------------------------
// Scratch (device globals; no dynamic allocation allowed)
// ---------------------------------------------------------------------------
__device__ float g_x[(size_t)PT * XPAD];                      // padded tf32 features
__device__ float g_featsT[(size_t)B_ * NV * H1_ * W1_ * D_];  // channel-last feats
__device__ float g_imgsT[(size_t)B_ * NV * H_ * W_ * 3];      // channel-last imgs
__device__ float g_proj[B_ * NV * 12];                        // P = K @ w2c[0:3,:]
__device__ float g_wpad[5 * DH * WS_STRIDE];                  // padded tf32 weights

// ---------------------------------------------------------------------------
// helpers
// ---------------------------------------------------------------------------
__device__ __forceinline__ float to_tf32(float x) {
    uint32_t r;
    asm("cvt.rna.tf32.f32 %0, %1;" : "=r"(r) : "f"(x));
    return __uint_as_float(r);
}

__device__ __forceinline__ void mma_tf32(float (&d)[4], const uint32_t (&a)[4],
                                         const uint32_t (&b)[2]) {
    asm volatile(
        "mma.sync.aligned.m16n8k8.row.col.f32.tf32.tf32.f32 "
        "{%0,%1,%2,%3}, {%4,%5,%6,%7}, {%8,%9}, {%0,%1,%2,%3};"
        : "+f"(d[0]), "+f"(d[1]), "+f"(d[2]), "+f"(d[3])
        : "r"(a[0]), "r"(a[1]), "r"(a[2]), "r"(a[3]), "r"(b[0]), "r"(b[1]));
}

__device__ __forceinline__ uint32_t smem_u32(const void* p) {
    return (uint32_t)__cvta_generic_to_shared(p);
}

__device__ __forceinline__ void cp16(uint32_t saddr, const void* g) {
    asm volatile("cp.async.cg.shared.global [%0], [%1], 16;" :: "r"(saddr), "l"(g));
}
#define CP_COMMIT() asm volatile("cp.async.commit_group;")
#define CP_WAIT(N)  asm volatile("cp.async.wait_group %0;" :: "n"(N))

// ---------------------------------------------------------------------------
// Kernel 0: per-(b,v) projection matrices  P = K @ inv(c2w)[0:3, :]
// ---------------------------------------------------------------------------
__global__ void proj_kernel(const float* __restrict__ cams) {
    int i = threadIdx.x;
    if (i >= B_ * NV) return;
    const float* c = cams + i * 27;
    float K[9];
#pragma unroll
    for (int j = 0; j < 9; j++) K[j] = c[2 + j];
    float m[16];
#pragma unroll
    for (int j = 0; j < 16; j++) m[j] = c[11 + j];

    float inv[16];
    inv[0]  =  m[5]*m[10]*m[15] - m[5]*m[11]*m[14] - m[9]*m[6]*m[15] + m[9]*m[7]*m[14] + m[13]*m[6]*m[11] - m[13]*m[7]*m[10];
    inv[4]  = -m[4]*m[10]*m[15] + m[4]*m[11]*m[14] + m[8]*m[6]*m[15] - m[8]*m[7]*m[14] - m[12]*m[6]*m[11] + m[12]*m[7]*m[10];
    inv[8]  =  m[4]*m[9]*m[15]  - m[4]*m[11]*m[13] - m[8]*m[5]*m[15] + m[8]*m[7]*m[13] + m[12]*m[5]*m[11] - m[12]*m[7]*m[9];
    inv[12] = -m[4]*m[9]*m[14]  + m[4]*m[10]*m[13] + m[8]*m[5]*m[14] - m[8]*m[6]*m[13] - m[12]*m[5]*m[10] + m[12]*m[6]*m[9];
    inv[1]  = -m[1]*m[10]*m[15] + m[1]*m[11]*m[14] + m[9]*m[2]*m[15] - m[9]*m[3]*m[14] - m[13]*m[2]*m[11] + m[13]*m[3]*m[10];
    inv[5]  =  m[0]*m[10]*m[15] - m[0]*m[11]*m[14] - m[8]*m[2]*m[15] + m[8]*m[3]*m[14] + m[12]*m[2]*m[11] - m[12]*m[3]*m[10];
    inv[9]  = -m[0]*m[9]*m[15]  + m[0]*m[11]*m[13] + m[8]*m[1]*m[15] - m[8]*m[3]*m[13] - m[12]*m[1]*m[11] + m[12]*m[3]*m[9];
    inv[13] =  m[0]*m[9]*m[14]  - m[0]*m[10]*m[13] - m[8]*m[1]*m[14] + m[8]*m[2]*m[13] + m[12]*m[1]*m[10] - m[12]*m[2]*m[9];
    inv[2]  =  m[1]*m[6]*m[15]  - m[1]*m[7]*m[14]  - m[5]*m[2]*m[15] + m[5]*m[3]*m[14] + m[13]*m[2]*m[7]  - m[13]*m[3]*m[6];
    inv[6]  = -m[0]*m[6]*m[15]  + m[0]*m[7]*m[14]  + m[4]*m[2]*m[15] - m[4]*m[3]*m[14] - m[12]*m[2]*m[7]  + m[12]*m[3]*m[6];
    inv[10] =  m[0]*m[5]*m[15]  - m[0]*m[7]*m[13]  - m[4]*m[1]*m[15] + m[4]*m[3]*m[13] + m[12]*m[1]*m[7]  - m[12]*m[3]*m[5];
    inv[14] = -m[0]*m[5]*m[14]  + m[0]*m[6]*m[13]  + m[4]*m[1]*m[14] - m[4]*m[2]*m[13] - m[12]*m[1]*m[6]  + m[12]*m[2]*m[5];
    inv[3]  = -m[1]*m[6]*m[11]  + m[1]*m[7]*m[10]  + m[5]*m[2]*m[11] - m[5]*m[3]*m[10] - m[9]*m[2]*m[7]   + m[9]*m[3]*m[6];
    inv[7]  =  m[0]*m[6]*m[11]  - m[0]*m[7]*m[10]  - m[4]*m[2]*m[11] + m[4]*m[3]*m[10] + m[8]*m[2]*m[7]   - m[8]*m[3]*m[6];
    inv[11] = -m[0]*m[5]*m[11]  + m[0]*m[7]*m[9]   + m[4]*m[1]*m[11] - m[4]*m[3]*m[9]  - m[8]*m[1]*m[7]   + m[8]*m[3]*m[5];
    inv[15] =  m[0]*m[5]*m[10]  - m[0]*m[6]*m[9]   - m[4]*m[1]*m[10] + m[4]*m[2]*m[9]  + m[8]*m[1]*m[6]   - m[8]*m[2]*m[5];

    float det = m[0]*inv[0] + m[1]*inv[4] + m[2]*inv[8] + m[3]*inv[12];
    float id = 1.0f / det;
#pragma unroll
    for (int j = 0; j < 16; j++) inv[j] *= id;

#pragma unroll
    for (int r = 0; r < 3; r++) {
#pragma unroll
        for (int cc = 0; cc < 4; cc++) {
            float s = K[r*3+0]*inv[0*4+cc] + K[r*3+1]*inv[1*4+cc] + K[r*3+2]*inv[2*4+cc];
            g_proj[i*12 + r*4 + cc] = s;
        }
    }
}

// ---------------------------------------------------------------------------
// Weight prep: padded, tf32-rounded weight tiles for cp.async staging.
// layer 0: rows 0..71 (W0 70x128, 2 zero rows); layers 1..4: W1..W4 (128x128)
// ---------------------------------------------------------------------------
__global__ void wprep_kernel(const float* __restrict__ w0, const float* __restrict__ w1,
                             const float* __restrict__ w2, const float* __restrict__ w3,
                             const float* __restrict__ w4) {
    int o = blockIdx.x * blockDim.x + threadIdx.x;
    if (o >= 5 * DH * WS_STRIDE) return;
    int l = o / (DH * WS_STRIDE);
    int rem = o - l * DH * WS_STRIDE;
    int k = rem / WS_STRIDE;
    int n = rem - k * WS_STRIDE;
    float v = 0.f;
    if (n < DH) {
        if (l == 0) { if (k < INBASE) v = w0[k * DH + n]; }
        else {
            const float* w = (l == 1) ? w1 : (l == 2) ? w2 : (l == 3) ? w3 : w4;
            v = w[k * DH + n];
        }
    }
    g_wpad[o] = to_tf32(v);
}

// ---------------------------------------------------------------------------
// Transpose feats (B,Nv,D,H1,W1) -> (B,Nv,H1,W1,D)  and imgs similarly
// ---------------------------------------------------------------------------
__global__ void tfeat_kernel(const float* __restrict__ f) {
    int o = blockIdx.x * blockDim.x + threadIdx.x;
    if (o >= B_ * NV * H1_ * W1_ * D_) return;
    int c = o & (D_ - 1);
    int rest = o >> 5;
    int x = rest % W1_;
    int t2 = rest / W1_;
    int y = t2 % H1_;
    int bv = t2 / H1_;
    g_featsT[o] = f[((size_t)(bv * D_ + c)) * (H1_ * W1_) + y * W1_ + x];
}

__global__ void timg_kernel(const float* __restrict__ im) {
    int o = blockIdx.x * blockDim.x + threadIdx.x;
    if (o >= B_ * NV * H_ * W_ * 3) return;
    int c = o % 3;
    int rest = o / 3;
    int x = rest % W_;
    int t2 = rest / W_;
    int y = t2 % H_;
    int bv = t2 / H_;
    g_imgsT[o] = im[((size_t)(bv * 3 + c)) * (H_ * W_) + y * W_ + x];
}

// ---------------------------------------------------------------------------
// Kernel 1: project + bilinear sample + masked mean/var -> g_x [PT][72] (tf32)
// ---------------------------------------------------------------------------
__global__ void __launch_bounds__(256) featurize_kernel(const float* __restrict__ xyz) {
    int gp = blockIdx.x * blockDim.x + threadIdx.x;
    if (gp >= PT) return;
    int b = gp / NPB;

    float X = xyz[(size_t)gp * 3 + 0];
    float Y = xyz[(size_t)gp * 3 + 1];
    float Z = xyz[(size_t)gp * 3 + 2];

    float sum[35], sq[35];
#pragma unroll
    for (int i = 0; i < 35; i++) { sum[i] = 0.f; sq[i] = 0.f; }
    float s = 0.f;

    const float SX = (float)(W1_ - 1) / (float)(W_ - 1);
    const float SY = (float)(H1_ - 1) / (float)(H_ - 1);

    for (int v = 0; v < NV; v++) {
        const float* Pm = &g_proj[(b * NV + v) * 12];
        float pxn = Pm[0]*X + Pm[1]*Y + Pm[2]*Z  + Pm[3];
        float pyn = Pm[4]*X + Pm[5]*Y + Pm[6]*Z  + Pm[7];
        float pz  = Pm[8]*X + Pm[9]*Y + Pm[10]*Z + Pm[11];
        float d = fmaxf(pz, 1e-8f);
        float px = pxn / d;
        float py = pyn / d;
        bool inb = (pz > 1e-4f) && (px >= 0.f) && (px <= (float)(W_ - 1))
                                && (py >= 0.f) && (py <= (float)(H_ - 1));
        if (!inb) continue;
        s += 1.f;

        {   // image bilinear (3 ch, channel-last)
            float x0f = floorf(px), y0f = floorf(py);
            float wx = px - x0f, wy = py - y0f;
            int x0 = (int)x0f;
            int y0 = (int)y0f;
            int x1 = min(x0 + 1, W_ - 1);
            int y1 = min(y0 + 1, H_ - 1);
            float w00 = (1.f - wx) * (1.f - wy);
            float w01 = wx * (1.f - wy);
            float w10 = (1.f - wx) * wy;
            float w11 = wx * wy;
            const float* ib = g_imgsT + (size_t)(b * NV + v) * H_ * W_ * 3;
            const float* p00 = ib + (size_t)(y0 * W_ + x0) * 3;
            const float* p01 = ib + (size_t)(y0 * W_ + x1) * 3;
            const float* p10 = ib + (size_t)(y1 * W_ + x0) * 3;
            const float* p11 = ib + (size_t)(y1 * W_ + x1) * 3;
#pragma unroll
            for (int c = 0; c < 3; c++) {
                float val = p00[c]*w00 + p01[c]*w01 + p10[c]*w10 + p11[c]*w11;
                sum[c] += val;
                sq[c]  += val * val;
            }
        }

        {   // feature bilinear (32 ch, channel-last, float4 taps)
            float fx = px * SX;
            float fy = py * SY;
            float x0f = floorf(fx), y0f = floorf(fy);
            float wx = fx - x0f, wy = fy - y0f;
            int x0 = (int)x0f;
            int y0 = (int)y0f;
            int x1 = min(x0 + 1, W1_ - 1);
            int y1 = min(y0 + 1, H1_ - 1);
            float w00 = (1.f - wx) * (1.f - wy);
            float w01 = wx * (1.f - wy);
            float w10 = (1.f - wx) * wy;
            float w11 = wx * wy;
            const float* fb = g_featsT + (size_t)(b * NV + v) * H1_ * W1_ * D_;
            const float4* t00 = reinterpret_cast<const float4*>(fb + (size_t)(y0 * W1_ + x0) * D_);
            const float4* t01 = reinterpret_cast<const float4*>(fb + (size_t)(y0 * W1_ + x1) * D_);
            const float4* t10 = reinterpret_cast<const float4*>(fb + (size_t)(y1 * W1_ + x0) * D_);
            const float4* t11 = reinterpret_cast<const float4*>(fb + (size_t)(y1 * W1_ + x1) * D_);
#pragma unroll
            for (int q = 0; q < 8; q++) {
                float4 a = t00[q], bb = t01[q], cc = t10[q], dd = t11[q];
                float v0 = a.x*w00 + bb.x*w01 + cc.x*w10 + dd.x*w11;
                float v1 = a.y*w00 + bb.y*w01 + cc.y*w10 + dd.y*w11;
                float v2 = a.z*w00 + bb.z*w01 + cc.z*w10 + dd.z*w11;
                float v3 = a.w*w00 + bb.w*w01 + cc.w*w10 + dd.w*w11;
                int o = 3 + q * 4;
                sum[o+0] += v0; sq[o+0] += v0 * v0;
                sum[o+1] += v1; sq[o+1] += v1 * v1;
                sum[o+2] += v2; sq[o+2] += v2 * v2;
                sum[o+3] += v3; sq[o+3] += v3 * v3;
            }
        }
    }

    float denom = s + 1e-6f;
    float invd = 1.f / denom;
    float alpha = s * invd;
    float* xo = g_x + (size_t)gp * XPAD;
#pragma unroll
    for (int i = 0; i < 35; i++) {
        float m  = sum[i] * invd;
        float e2 = sq[i] * invd;
        xo[i]      = to_tf32(m);
        xo[35 + i] = to_tf32(e2 - (2.f - alpha) * m * m);
    }
    xo[70] = 0.f;
    xo[71] = 0.f;
}

// ---------------------------------------------------------------------------
// Kernel 2: fused MLP chain, tf32 mma.m16n8k8, 512 threads (16 warps, 4x4),
// warp tile 32x32, cp.async double-buffered weights.
// ---------------------------------------------------------------------------
template <int KSTEPS>
__device__ __forceinline__ void mma_gemm(const float* __restrict__ act,
                                         const float* __restrict__ ws,
                                         float (&acc)[2][4][4],
                                         int lane, int m_blk, int n_blk) {
#pragma unroll
    for (int mi = 0; mi < 2; mi++)
#pragma unroll
        for (int ni = 0; ni < 4; ni++)
#pragma unroll
            for (int j = 0; j < 4; j++) acc[mi][ni][j] = 0.f;

    const int r = lane >> 2;
    const int c = lane & 3;

#pragma unroll
    for (int kt = 0; kt < KSTEPS; kt++) {
        const int k0 = kt * 8;
        uint32_t a[2][4];
#pragma unroll
        for (int mi = 0; mi < 2; mi++) {
            const float* ab = act + (m_blk * 32 + mi * 16) * ACT_STRIDE + k0;
            a[mi][0] = __float_as_uint(ab[r * ACT_STRIDE + c]);
            a[mi][1] = __float_as_uint(ab[(r + 8) * ACT_STRIDE + c]);
            a[mi][2] = __float_as_uint(ab[r * ACT_STRIDE + c + 4]);
            a[mi][3] = __float_as_uint(ab[(r + 8) * ACT_STRIDE + c + 4]);
        }
        uint32_t bfr[4][2];
#pragma unroll
        for (int ni = 0; ni < 4; ni++) {
            const float* bb = ws + (k0 + c) * WS_STRIDE + n_blk * 32 + ni * 8 + r;
            bfr[ni][0] = __float_as_uint(bb[0]);
            bfr[ni][1] = __float_as_uint(bb[4 * WS_STRIDE]);
        }
#pragma unroll
        for (int mi = 0; mi < 2; mi++)
#pragma unroll
            for (int ni = 0; ni < 4; ni++)
                mma_tf32(acc[mi][ni], a[mi], bfr[ni]);
    }
}

__device__ __forceinline__ void epilogue(float* __restrict__ act,
                                         const float* __restrict__ bs,
                                         float (&acc)[2][4][4],
                                         int lane, int m_blk, int n_blk,
                                         bool leaky) {
    const int r = lane >> 2;
    const int c2 = (lane & 3) * 2;
#pragma unroll
    for (int mi = 0; mi < 2; mi++) {
        const int row0 = m_blk * 32 + mi * 16 + r;
#pragma unroll
        for (int ni = 0; ni < 4; ni++) {
            const int col = n_blk * 32 + ni * 8 + c2;
            float v0 = acc[mi][ni][0] + bs[col];
            float v1 = acc[mi][ni][1] + bs[col + 1];
            float v2 = acc[mi][ni][2] + bs[col];
            float v3 = acc[mi][ni][3] + bs[col + 1];
            if (leaky) {
                v0 = v0 > 0.f ? v0 : 0.01f * v0;
                v1 = v1 > 0.f ? v1 : 0.01f * v1;
                v2 = v2 > 0.f ? v2 : 0.01f * v2;
                v3 = v3 > 0.f ? v3 : 0.01f * v3;
            }
            act[row0 * ACT_STRIDE + col]           = to_tf32(v0);
            act[row0 * ACT_STRIDE + col + 1]       = to_tf32(v1);
            act[(row0 + 8) * ACT_STRIDE + col]     = to_tf32(v2);
            act[(row0 + 8) * ACT_STRIDE + col + 1] = to_tf32(v3);
        }
    }
}

__global__ void __launch_bounds__(MLP_THREADS) mlp_mma_kernel(
    const float* __restrict__ b0, const float* __restrict__ b1,
    const float* __restrict__ b2, const float* __restrict__ b3,
    const float* __restrict__ b4,
    const float* __restrict__ w5, const float* __restrict__ b5,
    const float* __restrict__ dw, const float* __restrict__ db,
    float* __restrict__ out) {

    extern __shared__ float sm[];
    float* act  = sm;                         // 128 * ACT_STRIDE
    float* wbuf = act + 128 * ACT_STRIDE;     // 2 * 128 * WS_STRIDE
    float* bias = wbuf + 2 * 128 * WS_STRIDE; // 5 * 128
    float* w5s  = bias + 5 * DH;              // 384
    float* dws  = w5s + DH * 3;               // 128

    const int tid  = threadIdx.x;
    const int lane = tid & 31;
    const int warp = tid >> 5;
    const int m_blk = warp & 3;
    const int n_blk = warp >> 2;
    const int p0 = blockIdx.x * TM;

    const uint32_t s_act  = smem_u32(act);
    const uint32_t s_wb0  = smem_u32(wbuf);
    const uint32_t s_wb1  = smem_u32(wbuf + 128 * WS_STRIDE);

    // ---- group 0: act tile (128 rows x 18 chunks) + W0 (72 rows x 34 chunks)
    {
        const float* gx = g_x + (size_t)p0 * XPAD;
        for (int i = tid; i < 128 * (XPAD / 4); i += MLP_THREADS) {
            int row = i / (XPAD / 4), ch = i - row * (XPAD / 4);
            cp16(s_act + (uint32_t)(row * ACT_STRIDE + ch * 4) * 4,
                 gx + (size_t)row * XPAD + ch * 4);
        }
        const float* gw = g_wpad;  // layer 0
        for (int i = tid; i < 72 * (WS_STRIDE / 4); i += MLP_THREADS)
            cp16(s_wb0 + (uint32_t)i * 16, gw + i * 4);
    }
    CP_COMMIT();
    // ---- group 1: W1 -> wbuf1
    {
        const float* gw = g_wpad + 1 * DH * WS_STRIDE;
        for (int i = tid; i < 128 * (WS_STRIDE / 4); i += MLP_THREADS)
            cp16(s_wb1 + (uint32_t)i * 16, gw + i * 4);
    }
    CP_COMMIT();

    // biases + heads (regular loads, overlap with cp.async)
    if (tid < DH) {
        bias[0 * DH + tid] = b0[tid];
        bias[1 * DH + tid] = b1[tid];
        bias[2 * DH + tid] = b2[tid];
        bias[3 * DH + tid] = b3[tid];
        bias[4 * DH + tid] = b4[tid];
        dws[tid] = dw[tid];
    }
    for (int i = tid; i < DH * 3; i += MLP_THREADS) w5s[i] = w5[i];

    float acc[2][4][4];

#pragma unroll 1
    for (int l = 0; l < 5; l++) {
        if (l < 4) { CP_WAIT(1); } else { CP_WAIT(0); }
        __syncthreads();   // weights for layer l visible; act from epilogue l-1 visible

        if (l == 1 && tid < TM) {
            // sigma head from pf (act holds layer-0 output)
            float sacc = db[0];
#pragma unroll 4
            for (int kk = 0; kk < DH; kk++) {
                int k = (kk + lane) & (DH - 1);
                sacc = fmaf(act[tid * ACT_STRIDE + k], dws[k], sacc);
            }
            out[(size_t)(p0 + tid) * 4 + 3] = fmaxf(sacc, 0.f);
        }

        const float* ws = wbuf + (l & 1) * 128 * WS_STRIDE;
        if (l == 0) mma_gemm<9>(act, ws, acc, lane, m_blk, n_blk);
        else        mma_gemm<16>(act, ws, acc, lane, m_blk, n_blk);
        __syncthreads();   // all reads of wbuf[l&1] done

        if (l + 2 <= 4) {  // prefetch W(l+2) into the buffer just freed
            const float* gw = g_wpad + (size_t)(l + 2) * DH * WS_STRIDE;
            uint32_t dst = (l & 1) ? s_wb1 : s_wb0;
            for (int i = tid; i < 128 * (WS_STRIDE / 4); i += MLP_THREADS)
                cp16(dst + (uint32_t)i * 16, gw + i * 4);
        }
        CP_COMMIT();       // always commit (possibly-empty group) to keep counts uniform

        epilogue(act, bias + l * DH, acc, lane, m_blk, n_blk, l > 0);
    }
    __syncthreads();

    // rgb head: tanh(h4 @ w5 + b5)
    if (tid < TM) {
        float r0 = b5[0], r1 = b5[1], r2 = b5[2];
#pragma unroll 4
        for (int kk = 0; kk < DH; kk++) {
            int k = (kk + lane) & (DH - 1);
            float hv = act[tid * ACT_STRIDE + k];
            r0 = fmaf(hv, w5s[k * 3 + 0], r0);
            r1 = fmaf(hv, w5s[k * 3 + 1], r1);
            r2 = fmaf(hv, w5s[k * 3 + 2], r2);
        }
        size_t o = (size_t)(p0 + tid) * 4;
        out[o + 0] = tanhf(r0);
        out[o + 1] = tanhf(r1);
        out[o + 2] = tanhf(r2);
    }
}

// ---------------------------------------------------------------------------
// Launch
// ---------------------------------------------------------------------------
extern "C" void kernel_launch(void* const* d_in, const int* in_sizes, int n_in,
                              void* d_out, int out_size) {
    const float* xyz       = (const float*)d_in[0];
    // d_in[1] = cam (unused by reference)
    const float* src_imgs  = (const float*)d_in[2];
    const float* src_cams  = (const float*)d_in[3];
    const float* src_feats = (const float*)d_in[4];
    const float* w0 = (const float*)d_in[5];
    const float* b0 = (const float*)d_in[6];
    const float* w1 = (const float*)d_in[7];
    const float* b1 = (const float*)d_in[8];
    const float* w2 = (const float*)d_in[9];
    const float* b2 = (const float*)d_in[10];
    const float* w3 = (const float*)d_in[11];
    const float* b3 = (const float*)d_in[12];
    const float* w4 = (const float*)d_in[13];
    const float* b4 = (const float*)d_in[14];
    const float* w5 = (const float*)d_in[15];
    const float* b5 = (const float*)d_in[16];
    const float* dw = (const float*)d_in[17];
    const float* db = (const float*)d_in[18];
    float* out = (float*)d_out;

    const int smem_bytes =
        (128 * ACT_STRIDE + 2 * 128 * WS_STRIDE + 5 * DH + DH * 3 + DH) * (int)sizeof(float);
    cudaFuncSetAttribute(mlp_mma_kernel,
                         cudaFuncAttributeMaxDynamicSharedMemorySize, smem_bytes);

    proj_kernel<<<1, 32>>>(src_cams);
    wprep_kernel<<<(5 * DH * WS_STRIDE + 255) / 256, 256>>>(w0, w1, w2, w3, w4);
    tfeat_kernel<<<(B_ * NV * H1_ * W1_ * D_) / 256, 256>>>(src_feats);
    timg_kernel<<<(B_ * NV * H_ * W_ * 3 + 255) / 256, 256>>>(src_imgs);
    featurize_kernel<<<PT / 256, 256>>>(xyz);
    mlp_mma_kernel<<<PT / TM, MLP_THREADS, smem_bytes>>>(b0, b1, b2, b3, b4,
                                                         w5, b5, dw, db, out);
}

// round 7
// speedup vs baseline: 4.0690x; 1.2669x over previous
// Third submission of the round-5 kernel. Rounds 5 and 6 both died with
// broker/container-level errors (Trio nursery ExceptionGroup; "GB300 container
// failed twice" -- the same error round 0 produced with no kernel at all).
// The kernel has never been compiled or executed by the harness; resubmitting
// unchanged to preserve the post-mortem signal for the quad-split featurize.
#include <cuda_runtime.h>
#include <math.h>
#include <stdint.h>

// ---------------------------------------------------------------------------
// Problem constants (shapes fixed by setup_inputs)
// ---------------------------------------------------------------------------
#define B_ 2
#define NV 4
#define H_ 240
#define W_ 240
#define H1_ 120
#define W1_ 120
#define D_ 32
#define NPB 131072            // points per batch (Nr*Np = 2048*64)
#define PT (B_ * NPB)         // 262144 total points
#define INBASE 70             // 2*(D+3)
#define XPAD 72               // padded feature row (16B-aligned rows for cp.async)
#define DH 128                // hidden dim
#define TM 128                // point tile per block in MLP kernel
#define MLP_THREADS 512

#define ACT_STRIDE 132        // 132 % 32 == 4  -> A-frag LDS conflict-free, 528B row (16B mult)
#define WS_STRIDE  136        // 136 % 32 == 8  -> B-frag LDS conflict-free, 544B row (16B mult)

// ---------------------------------------------------------------------------
// Scratch (device globals; no dynamic allocation allowed)
// ---------------------------------------------------------------------------
__device__ float g_x[(size_t)PT * XPAD];                      // padded tf32 features
__device__ float g_featsT[(size_t)B_ * NV * H1_ * W1_ * D_];  // channel-last feats
__device__ float g_imgsT[(size_t)B_ * NV * H_ * W_ * 3];      // channel-last imgs
__device__ float g_proj[B_ * NV * 12];                        // P = K @ w2c[0:3,:]
__device__ float g_wpad[5 * DH * WS_STRIDE];                  // padded tf32 weights

// ---------------------------------------------------------------------------
// helpers
// ---------------------------------------------------------------------------
__device__ __forceinline__ float to_tf32(float x) {
    uint32_t r;
    asm("cvt.rna.tf32.f32 %0, %1;" : "=r"(r) : "f"(x));
    return __uint_as_float(r);
}

__device__ __forceinline__ void mma_tf32(float (&d)[4], const uint32_t (&a)[4],
                                         const uint32_t (&b)[2]) {
    asm volatile(
        "mma.sync.aligned.m16n8k8.row.col.f32.tf32.tf32.f32 "
        "{%0,%1,%2,%3}, {%4,%5,%6,%7}, {%8,%9}, {%0,%1,%2,%3};"
        : "+f"(d[0]), "+f"(d[1]), "+f"(d[2]), "+f"(d[3])
        : "r"(a[0]), "r"(a[1]), "r"(a[2]), "r"(a[3]), "r"(b[0]), "r"(b[1]));
}

__device__ __forceinline__ uint32_t smem_u32(const void* p) {
    return (uint32_t)__cvta_generic_to_shared(p);
}

__device__ __forceinline__ void cp16(uint32_t saddr, const void* g) {
    asm volatile("cp.async.cg.shared.global [%0], [%1], 16;" :: "r"(saddr), "l"(g));
}
#define CP_COMMIT() asm volatile("cp.async.commit_group;")
#define CP_WAIT(N)  asm volatile("cp.async.wait_group %0;" :: "n"(N))

// ---------------------------------------------------------------------------
// Kernel 0: per-(b,v) projection matrices  P = K @ inv(c2w)[0:3, :]
// ---------------------------------------------------------------------------
__global__ void proj_kernel(const float* __restrict__ cams) {
    int i = threadIdx.x;
    if (i >= B_ * NV) return;
    const float* c = cams + i * 27;
    float K[9];
#pragma unroll
    for (int j = 0; j < 9; j++) K[j] = c[2 + j];
    float m[16];
#pragma unroll
    for (int j = 0; j < 16; j++) m[j] = c[11 + j];

    float inv[16];
    inv[0]  =  m[5]*m[10]*m[15] - m[5]*m[11]*m[14] - m[9]*m[6]*m[15] + m[9]*m[7]*m[14] + m[13]*m[6]*m[11] - m[13]*m[7]*m[10];
    inv[4]  = -m[4]*m[10]*m[15] + m[4]*m[11]*m[14] + m[8]*m[6]*m[15] - m[8]*m[7]*m[14] - m[12]*m[6]*m[11] + m[12]*m[7]*m[10];
    inv[8]  =  m[4]*m[9]*m[15]  - m[4]*m[11]*m[13] - m[8]*m[5]*m[15] + m[8]*m[7]*m[13] + m[12]*m[5]*m[11] - m[12]*m[7]*m[9];
    inv[12] = -m[4]*m[9]*m[14]  + m[4]*m[10]*m[13] + m[8]*m[5]*m[14] - m[8]*m[6]*m[13] - m[12]*m[5]*m[10] + m[12]*m[6]*m[9];
    inv[1]  = -m[1]*m[10]*m[15] + m[1]*m[11]*m[14] + m[9]*m[2]*m[15] - m[9]*m[3]*m[14] - m[13]*m[2]*m[11] + m[13]*m[3]*m[10];
    inv[5]  =  m[0]*m[10]*m[15] - m[0]*m[11]*m[14] - m[8]*m[2]*m[15] + m[8]*m[3]*m[14] + m[12]*m[2]*m[11] - m[12]*m[3]*m[10];
    inv[9]  = -m[0]*m[9]*m[15]  + m[0]*m[11]*m[13] + m[8]*m[1]*m[15] - m[8]*m[3]*m[13] - m[12]*m[1]*m[11] + m[12]*m[3]*m[9];
    inv[13] =  m[0]*m[9]*m[14]  - m[0]*m[10]*m[13] - m[8]*m[1]*m[14] + m[8]*m[2]*m[13] + m[12]*m[1]*m[10] - m[12]*m[2]*m[9];
    inv[2]  =  m[1]*m[6]*m[15]  - m[1]*m[7]*m[14]  - m[5]*m[2]*m[15] + m[5]*m[3]*m[14] + m[13]*m[2]*m[7]  - m[13]*m[3]*m[6];
    inv[6]  = -m[0]*m[6]*m[15]  + m[0]*m[7]*m[14]  + m[4]*m[2]*m[15] - m[4]*m[3]*m[14] - m[12]*m[2]*m[7]  + m[12]*m[3]*m[6];
    inv[10] =  m[0]*m[5]*m[15]  - m[0]*m[7]*m[13]  - m[4]*m[1]*m[15] + m[4]*m[3]*m[13] + m[12]*m[1]*m[7]  - m[12]*m[3]*m[5];
    inv[14] = -m[0]*m[5]*m[14]  + m[0]*m[6]*m[13]  + m[4]*m[1]*m[14] - m[4]*m[2]*m[13] - m[12]*m[1]*m[6]  + m[12]*m[2]*m[5];
    inv[3]  = -m[1]*m[6]*m[11]  + m[1]*m[7]*m[10]  + m[5]*m[2]*m[11] - m[5]*m[3]*m[10] - m[9]*m[2]*m[7]   + m[9]*m[3]*m[6];
    inv[7]  =  m[0]*m[6]*m[11]  - m[0]*m[7]*m[10]  - m[4]*m[2]*m[11] + m[4]*m[3]*m[10] + m[8]*m[2]*m[7]   - m[8]*m[3]*m[6];
    inv[11] = -m[0]*m[5]*m[11]  + m[0]*m[7]*m[9]   + m[4]*m[1]*m[11] - m[4]*m[3]*m[9]  - m[8]*m[1]*m[7]   + m[8]*m[3]*m[5];
    inv[15] =  m[0]*m[5]*m[10]  - m[0]*m[6]*m[9]   - m[4]*m[1]*m[10] + m[4]*m[2]*m[9]  + m[8]*m[1]*m[6]   - m[8]*m[2]*m[5];

    float det = m[0]*inv[0] + m[1]*inv[4] + m[2]*inv[8] + m[3]*inv[12];
    float id = 1.0f / det;
#pragma unroll
    for (int j = 0; j < 16; j++) inv[j] *= id;

#pragma unroll
    for (int r = 0; r < 3; r++) {
#pragma unroll
        for (int cc = 0; cc < 4; cc++) {
            float s = K[r*3+0]*inv[0*4+cc] + K[r*3+1]*inv[1*4+cc] + K[r*3+2]*inv[2*4+cc];
            g_proj[i*12 + r*4 + cc] = s;
        }
    }
}

// ---------------------------------------------------------------------------
// Weight prep: padded, tf32-rounded weight tiles for cp.async staging.
// ---------------------------------------------------------------------------
__global__ void wprep_kernel(const float* __restrict__ w0, const float* __restrict__ w1,
                             const float* __restrict__ w2, const float* __restrict__ w3,
                             const float* __restrict__ w4) {
    int o = blockIdx.x * blockDim.x + threadIdx.x;
    if (o >= 5 * DH * WS_STRIDE) return;
    int l = o / (DH * WS_STRIDE);
    int rem = o - l * DH * WS_STRIDE;
    int k = rem / WS_STRIDE;
    int n = rem - k * WS_STRIDE;
    float v = 0.f;
    if (n < DH) {
        if (l == 0) { if (k < INBASE) v = w0[k * DH + n]; }
        else {
            const float* w = (l == 1) ? w1 : (l == 2) ? w2 : (l == 3) ? w3 : w4;
            v = w[k * DH + n];
        }
    }
    g_wpad[o] = to_tf32(v);
}

// ---------------------------------------------------------------------------
// Transpose feats (B,Nv,D,H1,W1) -> (B,Nv,H1,W1,D)  and imgs similarly
// ---------------------------------------------------------------------------
__global__ void tfeat_kernel(const float* __restrict__ f) {
    int o = blockIdx.x * blockDim.x + threadIdx.x;
    if (o >= B_ * NV * H1_ * W1_ * D_) return;
    int c = o & (D_ - 1);
    int rest = o >> 5;
    int x = rest % W1_;
    int t2 = rest / W1_;
    int y = t2 % H1_;
    int bv = t2 / H1_;
    g_featsT[o] = f[((size_t)(bv * D_ + c)) * (H1_ * W1_) + y * W1_ + x];
}

__global__ void timg_kernel(const float* __restrict__ im) {
    int o = blockIdx.x * blockDim.x + threadIdx.x;
    if (o >= B_ * NV * H_ * W_ * 3) return;
    int c = o % 3;
    int rest = o / 3;
    int x = rest % W_;
    int t2 = rest / W_;
    int y = t2 % H_;
    int bv = t2 / H_;
    g_imgsT[o] = im[((size_t)(bv * 3 + c)) * (H_ * W_) + y * W_ + x];
}

// ---------------------------------------------------------------------------
// Kernel 1 (quad version): 4 threads per point. Thread q owns feature
// channels [8q, 8q+8) and image channel q (q<3). Low regs -> high occupancy.
// ---------------------------------------------------------------------------
__global__ void __launch_bounds__(256) featurize_kernel(const float* __restrict__ xyz) {
    int t = blockIdx.x * blockDim.x + threadIdx.x;
    int gp = t >> 2;
    int q  = t & 3;
    if (gp >= PT) return;
    int b = gp / NPB;

    float X = xyz[(size_t)gp * 3 + 0];
    float Y = xyz[(size_t)gp * 3 + 1];
    float Z = xyz[(size_t)gp * 3 + 2];

    float fs[8], fq[8];
#pragma unroll
    for (int i = 0; i < 8; i++) { fs[i] = 0.f; fq[i] = 0.f; }
    float rs = 0.f, rq = 0.f;
    float s = 0.f;

    const float SX = (float)(W1_ - 1) / (float)(W_ - 1);
    const float SY = (float)(H1_ - 1) / (float)(H_ - 1);

#pragma unroll
    for (int v = 0; v < NV; v++) {
        const float* Pm = &g_proj[(b * NV + v) * 12];
        float pxn = Pm[0]*X + Pm[1]*Y + Pm[2]*Z  + Pm[3];
        float pyn = Pm[4]*X + Pm[5]*Y + Pm[6]*Z  + Pm[7];
        float pz  = Pm[8]*X + Pm[9]*Y + Pm[10]*Z + Pm[11];
        float d = fmaxf(pz, 1e-8f);
        float px = pxn / d;
        float py = pyn / d;
        bool inb = (pz > 1e-4f) && (px >= 0.f) && (px <= (float)(W_ - 1))
                                && (py >= 0.f) && (py <= (float)(H_ - 1));
        if (!inb) continue;
        s += 1.f;

        // --- image bilinear: thread q (<3) handles channel q ---
        if (q < 3) {
            float x0f = floorf(px), y0f = floorf(py);
            float wx = px - x0f, wy = py - y0f;
            int x0 = (int)x0f;
            int y0 = (int)y0f;
            int x1 = min(x0 + 1, W_ - 1);
            int y1 = min(y0 + 1, H_ - 1);
            float w00 = (1.f - wx) * (1.f - wy);
            float w01 = wx * (1.f - wy);
            float w10 = (1.f - wx) * wy;
            float w11 = wx * wy;
            const float* ib = g_imgsT + (size_t)(b * NV + v) * H_ * W_ * 3 + q;
            float val = ib[(size_t)(y0 * W_ + x0) * 3] * w00
                      + ib[(size_t)(y0 * W_ + x1) * 3] * w01
                      + ib[(size_t)(y1 * W_ + x0) * 3] * w10
                      + ib[(size_t)(y1 * W_ + x1) * 3] * w11;
            rs += val;
            rq += val * val;
        }

        // --- feature bilinear: thread q handles channels [8q, 8q+8) ---
        {
            float fx = px * SX;
            float fy = py * SY;
            float x0f = floorf(fx), y0f = floorf(fy);
            float wx = fx - x0f, wy = fy - y0f;
            int x0 = (int)x0f;
            int y0 = (int)y0f;
            int x1 = min(x0 + 1, W1_ - 1);
            int y1 = min(y0 + 1, H1_ - 1);
            float w00 = (1.f - wx) * (1.f - wy);
            float w01 = wx * (1.f - wy);
            float w10 = (1.f - wx) * wy;
            float w11 = wx * wy;
            const float* fb = g_featsT + (size_t)(b * NV + v) * H1_ * W1_ * D_ + q * 8;
            const float4* t00 = reinterpret_cast<const float4*>(fb + (size_t)(y0 * W1_ + x0) * D_);
            const float4* t01 = reinterpret_cast<const float4*>(fb + (size_t)(y0 * W1_ + x1) * D_);
            const float4* t10 = reinterpret_cast<const float4*>(fb + (size_t)(y1 * W1_ + x0) * D_);
            const float4* t11 = reinterpret_cast<const float4*>(fb + (size_t)(y1 * W1_ + x1) * D_);
#pragma unroll
            for (int hq = 0; hq < 2; hq++) {
                float4 a = t00[hq], bb = t01[hq], cc = t10[hq], dd = t11[hq];
                float v0 = a.x*w00 + bb.x*w01 + cc.x*w10 + dd.x*w11;
                float v1 = a.y*w00 + bb.y*w01 + cc.y*w10 + dd.y*w11;
                float v2 = a.z*w00 + bb.z*w01 + cc.z*w10 + dd.z*w11;
                float v3 = a.w*w00 + bb.w*w01 + cc.w*w10 + dd.w*w11;
                int o = hq * 4;
                fs[o+0] += v0; fq[o+0] += v0 * v0;
                fs[o+1] += v1; fq[o+1] += v1 * v1;
                fs[o+2] += v2; fq[o+2] += v2 * v2;
                fs[o+3] += v3; fq[o+3] += v3 * v3;
            }
        }
    }

    float denom = s + 1e-6f;
    float invd = 1.f / denom;
    float alpha = s * invd;
    float two_m_a = 2.f - alpha;
    float* xo = g_x + (size_t)gp * XPAD;

    if (q < 3) {
        float m  = rs * invd;
        float e2 = rq * invd;
        xo[q]      = to_tf32(m);
        xo[35 + q] = to_tf32(e2 - two_m_a * m * m);
    }
#pragma unroll
    for (int j = 0; j < 8; j++) {
        int i = 3 + q * 8 + j;
        float m  = fs[j] * invd;
        float e2 = fq[j] * invd;
        xo[i]      = to_tf32(m);
        xo[35 + i] = to_tf32(e2 - two_m_a * m * m);
    }
    if (q == 0) { xo[70] = 0.f; xo[71] = 0.f; }
}

// ---------------------------------------------------------------------------
// Kernel 2: fused MLP chain, tf32 mma.m16n8k8, 512 threads (16 warps, 4x4),
// warp tile 32x32, cp.async double-buffered weights.
// ---------------------------------------------------------------------------
template <int KSTEPS>
__device__ __forceinline__ void mma_gemm(const float* __restrict__ act,
                                         const float* __restrict__ ws,
                                         float (&acc)[2][4][4],
                                         int lane, int m_blk, int n_blk) {
#pragma unroll
    for (int mi = 0; mi < 2; mi++)
#pragma unroll
        for (int ni = 0; ni < 4; ni++)
#pragma unroll
            for (int j = 0; j < 4; j++) acc[mi][ni][j] = 0.f;

    const int r = lane >> 2;
    const int c = lane & 3;

#pragma unroll
    for (int kt = 0; kt < KSTEPS; kt++) {
        const int k0 = kt * 8;
        uint32_t a[2][4];
#pragma unroll
        for (int mi = 0; mi < 2; mi++) {
            const float* ab = act + (m_blk * 32 + mi * 16) * ACT_STRIDE + k0;
            a[mi][0] = __float_as_uint(ab[r * ACT_STRIDE + c]);
            a[mi][1] = __float_as_uint(ab[(r + 8) * ACT_STRIDE + c]);
            a[mi][2] = __float_as_uint(ab[r * ACT_STRIDE + c + 4]);
            a[mi][3] = __float_as_uint(ab[(r + 8) * ACT_STRIDE + c + 4]);
        }
        uint32_t bfr[4][2];
#pragma unroll
        for (int ni = 0; ni < 4; ni++) {
            const float* bb = ws + (k0 + c) * WS_STRIDE + n_blk * 32 + ni * 8 + r;
            bfr[ni][0] = __float_as_uint(bb[0]);
            bfr[ni][1] = __float_as_uint(bb[4 * WS_STRIDE]);
        }
#pragma unroll
        for (int mi = 0; mi < 2; mi++)
#pragma unroll
            for (int ni = 0; ni < 4; ni++)
                mma_tf32(acc[mi][ni], a[mi], bfr[ni]);
    }
}

__device__ __forceinline__ void epilogue(float* __restrict__ act,
                                         const float* __restrict__ bs,
                                         float (&acc)[2][4][4],
                                         int lane, int m_blk, int n_blk,
                                         bool leaky) {
    const int r = lane >> 2;
    const int c2 = (lane & 3) * 2;
#pragma unroll
    for (int mi = 0; mi < 2; mi++) {
        const int row0 = m_blk * 32 + mi * 16 + r;
#pragma unroll
        for (int ni = 0; ni < 4; ni++) {
            const int col = n_blk * 32 + ni * 8 + c2;
            float v0 = acc[mi][ni][0] + bs[col];
            float v1 = acc[mi][ni][1] + bs[col + 1];
            float v2 = acc[mi][ni][2] + bs[col];
            float v3 = acc[mi][ni][3] + bs[col + 1];
            if (leaky) {
                v0 = v0 > 0.f ? v0 : 0.01f * v0;
                v1 = v1 > 0.f ? v1 : 0.01f * v1;
                v2 = v2 > 0.f ? v2 : 0.01f * v2;
                v3 = v3 > 0.f ? v3 : 0.01f * v3;
            }
            act[row0 * ACT_STRIDE + col]           = to_tf32(v0);
            act[row0 * ACT_STRIDE + col + 1]       = to_tf32(v1);
            act[(row0 + 8) * ACT_STRIDE + col]     = to_tf32(v2);
            act[(row0 + 8) * ACT_STRIDE + col + 1] = to_tf32(v3);
        }
    }
}

__global__ void __launch_bounds__(MLP_THREADS) mlp_mma_kernel(
    const float* __restrict__ b0, const float* __restrict__ b1,
    const float* __restrict__ b2, const float* __restrict__ b3,
    const float* __restrict__ b4,
    const float* __restrict__ w5, const float* __restrict__ b5,
    const float* __restrict__ dw, const float* __restrict__ db,
    float* __restrict__ out) {

    extern __shared__ float sm[];
    float* act  = sm;                         // 128 * ACT_STRIDE
    float* wbuf = act + 128 * ACT_STRIDE;     // 2 * 128 * WS_STRIDE
    float* bias = wbuf + 2 * 128 * WS_STRIDE; // 5 * 128
    float* w5s  = bias + 5 * DH;              // 384
    float* dws  = w5s + DH * 3;               // 128

    const int tid  = threadIdx.x;
    const int lane = tid & 31;
    const int warp = tid >> 5;
    const int m_blk = warp & 3;
    const int n_blk = warp >> 2;
    const int p0 = blockIdx.x * TM;

    const uint32_t s_act  = smem_u32(act);
    const uint32_t s_wb0  = smem_u32(wbuf);
    const uint32_t s_wb1  = smem_u32(wbuf + 128 * WS_STRIDE);

    // ---- group 0: act tile + W0
    {
        const float* gx = g_x + (size_t)p0 * XPAD;
        for (int i = tid; i < 128 * (XPAD / 4); i += MLP_THREADS) {
            int row = i / (XPAD / 4), ch = i - row * (XPAD / 4);
            cp16(s_act + (uint32_t)(row * ACT_STRIDE + ch * 4) * 4,
                 gx + (size_t)row * XPAD + ch * 4);
        }
        const float* gw = g_wpad;  // layer 0
        for (int i = tid; i < 72 * (WS_STRIDE / 4); i += MLP_THREADS)
            cp16(s_wb0 + (uint32_t)i * 16, gw + i * 4);
    }
    CP_COMMIT();
    // ---- group 1: W1 -> wbuf1
    {
        const float* gw = g_wpad + 1 * DH * WS_STRIDE;
        for (int i = tid; i < 128 * (WS_STRIDE / 4); i += MLP_THREADS)
            cp16(s_wb1 + (uint32_t)i * 16, gw + i * 4);
    }
    CP_COMMIT();

    // biases + heads (regular loads, overlap with cp.async)
    if (tid < DH) {
        bias[0 * DH + tid] = b0[tid];
        bias[1 * DH + tid] = b1[tid];
        bias[2 * DH + tid] = b2[tid];
        bias[3 * DH + tid] = b3[tid];
        bias[4 * DH + tid] = b4[tid];
        dws[tid] = dw[tid];
    }
    for (int i = tid; i < DH * 3; i += MLP_THREADS) w5s[i] = w5[i];

    float acc[2][4][4];

#pragma unroll 1
    for (int l = 0; l < 5; l++) {
        if (l < 4) { CP_WAIT(1); } else { CP_WAIT(0); }
        __syncthreads();   // weights for layer l visible; act from epilogue l-1 visible

        if (l == 1 && tid < TM) {
            // sigma head from pf (act holds layer-0 output)
            float sacc = db[0];
#pragma unroll 4
            for (int kk = 0; kk < DH; kk++) {
                int k = (kk + lane) & (DH - 1);
                sacc = fmaf(act[tid * ACT_STRIDE + k], dws[k], sacc);
            }
            out[(size_t)(p0 + tid) * 4 + 3] = fmaxf(sacc, 0.f);
        }

        const float* ws = wbuf + (l & 1) * 128 * WS_STRIDE;
        if (l == 0) mma_gemm<9>(act, ws, acc, lane, m_blk, n_blk);
        else        mma_gemm<16>(act, ws, acc, lane, m_blk, n_blk);
        __syncthreads();   // all reads of wbuf[l&1] done

        if (l + 2 <= 4) {  // prefetch W(l+2) into the buffer just freed
            const float* gw = g_wpad + (size_t)(l + 2) * DH * WS_STRIDE;
            uint32_t dst = (l & 1) ? s_wb1 : s_wb0;
            for (int i = tid; i < 128 * (WS_STRIDE / 4); i += MLP_THREADS)
                cp16(dst + (uint32_t)i * 16, gw + i * 4);
        }
        CP_COMMIT();       // keep group counts uniform

        epilogue(act, bias + l * DH, acc, lane, m_blk, n_blk, l > 0);
    }
    __syncthreads();

    // rgb head: tanh(h4 @ w5 + b5)
    if (tid < TM) {
        float r0 = b5[0], r1 = b5[1], r2 = b5[2];
#pragma unroll 4
        for (int kk = 0; kk < DH; kk++) {
            int k = (kk + lane) & (DH - 1);
            float hv = act[tid * ACT_STRIDE + k];
            r0 = fmaf(hv, w5s[k * 3 + 0], r0);
            r1 = fmaf(hv, w5s[k * 3 + 1], r1);
            r2 = fmaf(hv, w5s[k * 3 + 2], r2);
        }
        size_t o = (size_t)(p0 + tid) * 4;
        out[o + 0] = tanhf(r0);
        out[o + 1] = tanhf(r1);
        out[o + 2] = tanhf(r2);
    }
}

// ---------------------------------------------------------------------------
// Launch
// ---------------------------------------------------------------------------
extern "C" void kernel_launch(void* const* d_in, const int* in_sizes, int n_in,
                              void* d_out, int out_size) {
    const float* xyz       = (const float*)d_in[0];
    // d_in[1] = cam (unused by reference)
    const float* src_imgs  = (const float*)d_in[2];
    const float* src_cams  = (const float*)d_in[3];
    const float* src_feats = (const float*)d_in[4];
    const float* w0 = (const float*)d_in[5];
    const float* b0 = (const float*)d_in[6];
    const float* w1 = (const float*)d_in[7];
    const float* b1 = (const float*)d_in[8];
    const float* w2 = (const float*)d_in[9];
    const float* b2 = (const float*)d_in[10];
    const float* w3 = (const float*)d_in[11];
    const float* b3 = (const float*)d_in[12];
    const float* w4 = (const float*)d_in[13];
    const float* b4 = (const float*)d_in[14];
    const float* w5 = (const float*)d_in[15];
    const float* b5 = (const float*)d_in[16];
    const float* dw = (const float*)d_in[17];
    const float* db = (const float*)d_in[18];
    float* out = (float*)d_out;

    const int smem_bytes =
        (128 * ACT_STRIDE + 2 * 128 * WS_STRIDE + 5 * DH + DH * 3 + DH) * (int)sizeof(float);
    cudaFuncSetAttribute(mlp_mma_kernel,
                         cudaFuncAttributeMaxDynamicSharedMemorySize, smem_bytes);

    proj_kernel<<<1, 32>>>(src_cams);
    wprep_kernel<<<(5 * DH * WS_STRIDE + 255) / 256, 256>>>(w0, w1, w2, w3, w4);
    tfeat_kernel<<<(B_ * NV * H1_ * W1_ * D_) / 256, 256>>>(src_feats);
    timg_kernel<<<(B_ * NV * H_ * W_ * 3 + 255) / 256, 256>>>(src_imgs);
    featurize_kernel<<<(PT * 4) / 256, 256>>>(xyz);
    mlp_mma_kernel<<<PT / TM, MLP_THREADS, smem_bytes>>>(b0, b1, b2, b3, b4,
                                                         w5, b5, dw, db, out);
}

// round 8
// speedup vs baseline: 5.5072x; 1.3534x over previous
#include <cuda_runtime.h>
#include <cuda_fp16.h>
#include <math.h>
#include <stdint.h>

// ---------------------------------------------------------------------------
// Problem constants
// ---------------------------------------------------------------------------
#define B_ 2
#define NV 4
#define H_ 240
#define W_ 240
#define H1_ 120
#define W1_ 120
#define D_ 32
#define NPB 131072
#define PT (B_ * NPB)
#define INBASE 70
#define XPAD_H 80             // padded fp16 feature row (160 B, 16B multiple)
#define DH 128
#define TM 128
#define MLP_THREADS 512

#define ACT_W 136             // halves per act row = 272 B  (272 % 128 == 16 -> conflict-free)
#define ACT_W32 68            // 32-bit words per act row
#define WS_W 136              // halves per weight row [n][k], same stride trick
#define WS_W32 68
#define ACT_BYTES (128 * ACT_W * 2)   // 34816
#define WS_BYTES  (128 * WS_W * 2)    // 34816

// ---------------------------------------------------------------------------
// Scratch (device globals)
// ---------------------------------------------------------------------------
__device__ __half g_xh[(size_t)PT * XPAD_H];                  // fp16 features
__device__ float  g_featsT[(size_t)B_ * NV * H1_ * W1_ * D_]; // channel-last feats
__device__ float  g_imgsT[(size_t)B_ * NV * H_ * W_ * 3];     // channel-last imgs
__device__ float  g_proj[B_ * NV * 12];
__device__ __half g_wpadh[5 * 128 * WS_W];                    // fp16 weights, [l][n][k] transposed

// ---------------------------------------------------------------------------
// helpers
// ---------------------------------------------------------------------------
__device__ __forceinline__ void mma_f16(float (&d)[4], const uint32_t (&a)[4],
                                        const uint32_t (&b)[2]) {
    asm volatile(
        "mma.sync.aligned.m16n8k16.row.col.f32.f16.f16.f32 "
        "{%0,%1,%2,%3}, {%4,%5,%6,%7}, {%8,%9}, {%0,%1,%2,%3};"
        : "+f"(d[0]), "+f"(d[1]), "+f"(d[2]), "+f"(d[3])
        : "r"(a[0]), "r"(a[1]), "r"(a[2]), "r"(a[3]), "r"(b[0]), "r"(b[1]));
}

__device__ __forceinline__ uint32_t smem_u32(const void* p) {
    return (uint32_t)__cvta_generic_to_shared(p);
}

__device__ __forceinline__ void cp16(uint32_t saddr, const void* g) {
    asm volatile("cp.async.cg.shared.global [%0], [%1], 16;" :: "r"(saddr), "l"(g));
}
#define CP_COMMIT() asm volatile("cp.async.commit_group;")
#define CP_WAIT(N)  asm volatile("cp.async.wait_group %0;" :: "n"(N))

// ---------------------------------------------------------------------------
// Kernel 0: projection matrices  P = K @ inv(c2w)[0:3, :]
// ---------------------------------------------------------------------------
__global__ void proj_kernel(const float* __restrict__ cams) {
    int i = threadIdx.x;
    if (i >= B_ * NV) return;
    const float* c = cams + i * 27;
    float K[9];
#pragma unroll
    for (int j = 0; j < 9; j++) K[j] = c[2 + j];
    float m[16];
#pragma unroll
    for (int j = 0; j < 16; j++) m[j] = c[11 + j];

    float inv[16];
    inv[0]  =  m[5]*m[10]*m[15] - m[5]*m[11]*m[14] - m[9]*m[6]*m[15] + m[9]*m[7]*m[14] + m[13]*m[6]*m[11] - m[13]*m[7]*m[10];
    inv[4]  = -m[4]*m[10]*m[15] + m[4]*m[11]*m[14] + m[8]*m[6]*m[15] - m[8]*m[7]*m[14] - m[12]*m[6]*m[11] + m[12]*m[7]*m[10];
    inv[8]  =  m[4]*m[9]*m[15]  - m[4]*m[11]*m[13] - m[8]*m[5]*m[15] + m[8]*m[7]*m[13] + m[12]*m[5]*m[11] - m[12]*m[7]*m[9];
    inv[12] = -m[4]*m[9]*m[14]  + m[4]*m[10]*m[13] + m[8]*m[5]*m[14] - m[8]*m[6]*m[13] - m[12]*m[5]*m[10] + m[12]*m[6]*m[9];
    inv[1]  = -m[1]*m[10]*m[15] + m[1]*m[11]*m[14] + m[9]*m[2]*m[15] - m[9]*m[3]*m[14] - m[13]*m[2]*m[11] + m[13]*m[3]*m[10];
    inv[5]  =  m[0]*m[10]*m[15] - m[0]*m[11]*m[14] - m[8]*m[2]*m[15] + m[8]*m[3]*m[14] + m[12]*m[2]*m[11] - m[12]*m[3]*m[10];
    inv[9]  = -m[0]*m[9]*m[15]  + m[0]*m[11]*m[13] + m[8]*m[1]*m[15] - m[8]*m[3]*m[13] - m[12]*m[1]*m[11] + m[12]*m[3]*m[9];
    inv[13] =  m[0]*m[9]*m[14]  - m[0]*m[10]*m[13] - m[8]*m[1]*m[14] + m[8]*m[2]*m[13] + m[12]*m[1]*m[10] - m[12]*m[2]*m[9];
    inv[2]  =  m[1]*m[6]*m[15]  - m[1]*m[7]*m[14]  - m[5]*m[2]*m[15] + m[5]*m[3]*m[14] + m[13]*m[2]*m[7]  - m[13]*m[3]*m[6];
    inv[6]  = -m[0]*m[6]*m[15]  + m[0]*m[7]*m[14]  + m[4]*m[2]*m[15] - m[4]*m[3]*m[14] - m[12]*m[2]*m[7]  + m[12]*m[3]*m[6];
    inv[10] =  m[0]*m[5]*m[15]  - m[0]*m[7]*m[13]  - m[4]*m[1]*m[15] + m[4]*m[3]*m[13] + m[12]*m[1]*m[7]  - m[12]*m[3]*m[5];
    inv[14] = -m[0]*m[5]*m[14]  + m[0]*m[6]*m[13]  + m[4]*m[1]*m[14] - m[4]*m[2]*m[13] - m[12]*m[1]*m[6]  + m[12]*m[2]*m[5];
    inv[3]  = -m[1]*m[6]*m[11]  + m[1]*m[7]*m[10]  + m[5]*m[2]*m[11] - m[5]*m[3]*m[10] - m[9]*m[2]*m[7]   + m[9]*m[3]*m[6];
    inv[7]  =  m[0]*m[6]*m[11]  - m[0]*m[7]*m[10]  - m[4]*m[2]*m[11] + m[4]*m[3]*m[10] + m[8]*m[2]*m[7]   - m[8]*m[3]*m[6];
    inv[11] = -m[0]*m[5]*m[11]  + m[0]*m[7]*m[9]   + m[4]*m[1]*m[11] - m[4]*m[3]*m[9]  - m[8]*m[1]*m[7]   + m[8]*m[3]*m[5];
    inv[15] =  m[0]*m[5]*m[10]  - m[0]*m[6]*m[9]   - m[4]*m[1]*m[10] + m[4]*m[2]*m[9]  + m[8]*m[1]*m[6]   - m[8]*m[2]*m[5];

    float det = m[0]*inv[0] + m[1]*inv[4] + m[2]*inv[8] + m[3]*inv[12];
    float id = 1.0f / det;
#pragma unroll
    for (int j = 0; j < 16; j++) inv[j] *= id;

#pragma unroll
    for (int r = 0; r < 3; r++) {
#pragma unroll
        for (int cc = 0; cc < 4; cc++) {
            float s = K[r*3+0]*inv[0*4+cc] + K[r*3+1]*inv[1*4+cc] + K[r*3+2]*inv[2*4+cc];
            g_proj[i*12 + r*4 + cc] = s;
        }
    }
}

// ---------------------------------------------------------------------------
// Weight prep: fp16, transposed [l][n][k], k-padded to WS_W.
// layer 0: k<70 valid from W0[k][n]; layers 1..4: k<128 valid.
// ---------------------------------------------------------------------------
__global__ void wprep_kernel(const float* __restrict__ w0, const float* __restrict__ w1,
                             const float* __restrict__ w2, const float* __restrict__ w3,
                             const float* __restrict__ w4) {
    int o = blockIdx.x * blockDim.x + threadIdx.x;
    if (o >= 5 * 128 * WS_W) return;
    int l = o / (128 * WS_W);
    int rem = o - l * 128 * WS_W;
    int n = rem / WS_W;
    int k = rem - n * WS_W;
    float v = 0.f;
    if (l == 0) {
        if (k < INBASE) v = w0[k * DH + n];
    } else if (k < DH) {
        const float* w = (l == 1) ? w1 : (l == 2) ? w2 : (l == 3) ? w3 : w4;
        v = w[k * DH + n];
    }
    g_wpadh[o] = __float2half_rn(v);
}

// ---------------------------------------------------------------------------
// Transposes (channel-last staging)
// ---------------------------------------------------------------------------
__global__ void tfeat_kernel(const float* __restrict__ f) {
    int o = blockIdx.x * blockDim.x + threadIdx.x;
    if (o >= B_ * NV * H1_ * W1_ * D_) return;
    int c = o & (D_ - 1);
    int rest = o >> 5;
    int x = rest % W1_;
    int t2 = rest / W1_;
    int y = t2 % H1_;
    int bv = t2 / H1_;
    g_featsT[o] = f[((size_t)(bv * D_ + c)) * (H1_ * W1_) + y * W1_ + x];
}

__global__ void timg_kernel(const float* __restrict__ im) {
    int o = blockIdx.x * blockDim.x + threadIdx.x;
    if (o >= B_ * NV * H_ * W_ * 3) return;
    int c = o % 3;
    int rest = o / 3;
    int x = rest % W_;
    int t2 = rest / W_;
    int y = t2 % H_;
    int bv = t2 / H_;
    g_imgsT[o] = im[((size_t)(bv * 3 + c)) * (H_ * W_) + y * W_ + x];
}

// ---------------------------------------------------------------------------
// Kernel 1: quad featurize (4 threads/point) -> g_xh [PT][80] fp16
// ---------------------------------------------------------------------------
__global__ void __launch_bounds__(256) featurize_kernel(const float* __restrict__ xyz) {
    int t = blockIdx.x * blockDim.x + threadIdx.x;
    int gp = t >> 2;
    int q  = t & 3;
    if (gp >= PT) return;
    int b = gp / NPB;

    float X = xyz[(size_t)gp * 3 + 0];
    float Y = xyz[(size_t)gp * 3 + 1];
    float Z = xyz[(size_t)gp * 3 + 2];

    float fs[8], fq[8];
#pragma unroll
    for (int i = 0; i < 8; i++) { fs[i] = 0.f; fq[i] = 0.f; }
    float rs = 0.f, rq = 0.f;
    float s = 0.f;

    const float SX = (float)(W1_ - 1) / (float)(W_ - 1);
    const float SY = (float)(H1_ - 1) / (float)(H_ - 1);

#pragma unroll
    for (int v = 0; v < NV; v++) {
        const float* Pm = &g_proj[(b * NV + v) * 12];
        float pxn = Pm[0]*X + Pm[1]*Y + Pm[2]*Z  + Pm[3];
        float pyn = Pm[4]*X + Pm[5]*Y + Pm[6]*Z  + Pm[7];
        float pz  = Pm[8]*X + Pm[9]*Y + Pm[10]*Z + Pm[11];
        float d = fmaxf(pz, 1e-8f);
        float px = pxn / d;
        float py = pyn / d;
        bool inb = (pz > 1e-4f) && (px >= 0.f) && (px <= (float)(W_ - 1))
                                && (py >= 0.f) && (py <= (float)(H_ - 1));
        if (!inb) continue;
        s += 1.f;

        if (q < 3) {
            float x0f = floorf(px), y0f = floorf(py);
            float wx = px - x0f, wy = py - y0f;
            int x0 = (int)x0f;
            int y0 = (int)y0f;
            int x1 = min(x0 + 1, W_ - 1);
            int y1 = min(y0 + 1, H_ - 1);
            float w00 = (1.f - wx) * (1.f - wy);
            float w01 = wx * (1.f - wy);
            float w10 = (1.f - wx) * wy;
            float w11 = wx * wy;
            const float* ib = g_imgsT + (size_t)(b * NV + v) * H_ * W_ * 3 + q;
            float val = ib[(size_t)(y0 * W_ + x0) * 3] * w00
                      + ib[(size_t)(y0 * W_ + x1) * 3] * w01
                      + ib[(size_t)(y1 * W_ + x0) * 3] * w10
                      + ib[(size_t)(y1 * W_ + x1) * 3] * w11;
            rs += val;
            rq += val * val;
        }

        {
            float fx = px * SX;
            float fy = py * SY;
            float x0f = floorf(fx), y0f = floorf(fy);
            float wx = fx - x0f, wy = fy - y0f;
            int x0 = (int)x0f;
            int y0 = (int)y0f;
            int x1 = min(x0 + 1, W1_ - 1);
            int y1 = min(y0 + 1, H1_ - 1);
            float w00 = (1.f - wx) * (1.f - wy);
            float w01 = wx * (1.f - wy);
            float w10 = (1.f - wx) * wy;
            float w11 = wx * wy;
            const float* fb = g_featsT + (size_t)(b * NV + v) * H1_ * W1_ * D_ + q * 8;
            const float4* t00 = reinterpret_cast<const float4*>(fb + (size_t)(y0 * W1_ + x0) * D_);
            const float4* t01 = reinterpret_cast<const float4*>(fb + (size_t)(y0 * W1_ + x1) * D_);
            const float4* t10 = reinterpret_cast<const float4*>(fb + (size_t)(y1 * W1_ + x0) * D_);
            const float4* t11 = reinterpret_cast<const float4*>(fb + (size_t)(y1 * W1_ + x1) * D_);
#pragma unroll
            for (int hq = 0; hq < 2; hq++) {
                float4 a = t00[hq], bb = t01[hq], cc = t10[hq], dd = t11[hq];
                float v0 = a.x*w00 + bb.x*w01 + cc.x*w10 + dd.x*w11;
                float v1 = a.y*w00 + bb.y*w01 + cc.y*w10 + dd.y*w11;
                float v2 = a.z*w00 + bb.z*w01 + cc.z*w10 + dd.z*w11;
                float v3 = a.w*w00 + bb.w*w01 + cc.w*w10 + dd.w*w11;
                int o = hq * 4;
                fs[o+0] += v0; fq[o+0] += v0 * v0;
                fs[o+1] += v1; fq[o+1] += v1 * v1;
                fs[o+2] += v2; fq[o+2] += v2 * v2;
                fs[o+3] += v3; fq[o+3] += v3 * v3;
            }
        }
    }

    float denom = s + 1e-6f;
    float invd = 1.f / denom;
    float alpha = s * invd;
    float two_m_a = 2.f - alpha;
    __half* xo = g_xh + (size_t)gp * XPAD_H;

    if (q < 3) {
        float m  = rs * invd;
        float e2 = rq * invd;
        xo[q]      = __float2half_rn(m);
        xo[35 + q] = __float2half_rn(e2 - two_m_a * m * m);
    }
#pragma unroll
    for (int j = 0; j < 8; j++) {
        int i = 3 + q * 8 + j;
        float m  = fs[j] * invd;
        float e2 = fq[j] * invd;
        xo[i]      = __float2half_rn(m);
        xo[35 + i] = __float2half_rn(e2 - two_m_a * m * m);
    }
    if (q == 0) {
#pragma unroll
        for (int j = 70; j < XPAD_H; j++) xo[j] = __float2half_rn(0.f);
    }
}

// ---------------------------------------------------------------------------
// Kernel 2: fused MLP, fp16 mma.m16n8k16, 512 threads, 2 blocks/SM,
// cp.async double-buffered transposed weights.
// ---------------------------------------------------------------------------
template <int KSTEPS>
__device__ __forceinline__ void mma_gemm(const uint32_t* __restrict__ act32,
                                         const uint32_t* __restrict__ ws32,
                                         float (&acc)[2][4][4],
                                         int lane, int m_blk, int n_blk) {
#pragma unroll
    for (int mi = 0; mi < 2; mi++)
#pragma unroll
        for (int ni = 0; ni < 4; ni++)
#pragma unroll
            for (int j = 0; j < 4; j++) acc[mi][ni][j] = 0.f;

    const int r = lane >> 2;
    const int cp = lane & 3;     // half2 index within 8-half group

#pragma unroll
    for (int kt = 0; kt < KSTEPS; kt++) {
        const int k32 = kt * 8;  // 16 halves per step = 8 words
        uint32_t a[2][4];
#pragma unroll
        for (int mi = 0; mi < 2; mi++) {
            const int base = (m_blk * 32 + mi * 16 + r) * ACT_W32 + k32 + cp;
            a[mi][0] = act32[base];
            a[mi][1] = act32[base + 8 * ACT_W32];
            a[mi][2] = act32[base + 4];
            a[mi][3] = act32[base + 8 * ACT_W32 + 4];
        }
        uint32_t bf[4][2];
#pragma unroll
        for (int ni = 0; ni < 4; ni++) {
            const int n = n_blk * 32 + ni * 8 + r;
            const int bbase = n * WS_W32 + k32 + cp;
            bf[ni][0] = ws32[bbase];
            bf[ni][1] = ws32[bbase + 4];
        }
#pragma unroll
        for (int mi = 0; mi < 2; mi++)
#pragma unroll
            for (int ni = 0; ni < 4; ni++)
                mma_f16(acc[mi][ni], a[mi], bf[ni]);
    }
}

__device__ __forceinline__ void epilogue(uint32_t* __restrict__ act32,
                                         const float* __restrict__ bs,
                                         float (&acc)[2][4][4],
                                         int lane, int m_blk, int n_blk,
                                         bool leaky) {
    const int r = lane >> 2;
    const int cp = lane & 3;
#pragma unroll
    for (int mi = 0; mi < 2; mi++) {
        const int row0 = m_blk * 32 + mi * 16 + r;
#pragma unroll
        for (int ni = 0; ni < 4; ni++) {
            const int col = n_blk * 32 + ni * 8 + cp * 2;
            float v0 = acc[mi][ni][0] + bs[col];
            float v1 = acc[mi][ni][1] + bs[col + 1];
            float v2 = acc[mi][ni][2] + bs[col];
            float v3 = acc[mi][ni][3] + bs[col + 1];
            if (leaky) {
                v0 = v0 > 0.f ? v0 : 0.01f * v0;
                v1 = v1 > 0.f ? v1 : 0.01f * v1;
                v2 = v2 > 0.f ? v2 : 0.01f * v2;
                v3 = v3 > 0.f ? v3 : 0.01f * v3;
            }
            __half2 h01 = __halves2half2(__float2half_rn(v0), __float2half_rn(v1));
            __half2 h23 = __halves2half2(__float2half_rn(v2), __float2half_rn(v3));
            act32[row0 * ACT_W32 + col / 2]       = *reinterpret_cast<uint32_t*>(&h01);
            act32[(row0 + 8) * ACT_W32 + col / 2] = *reinterpret_cast<uint32_t*>(&h23);
        }
    }
}

__global__ void __launch_bounds__(MLP_THREADS, 2) mlp_mma_kernel(
    const float* __restrict__ b0, const float* __restrict__ b1,
    const float* __restrict__ b2, const float* __restrict__ b3,
    const float* __restrict__ b4,
    const float* __restrict__ w5, const float* __restrict__ b5,
    const float* __restrict__ dw, const float* __restrict__ db,
    float* __restrict__ out) {

    extern __shared__ char smem[];
    uint32_t* act32 = reinterpret_cast<uint32_t*>(smem);                 // ACT_BYTES
    uint32_t* wbuf32 = reinterpret_cast<uint32_t*>(smem + ACT_BYTES);    // 2 * WS_BYTES
    float* bias = reinterpret_cast<float*>(smem + ACT_BYTES + 2 * WS_BYTES); // 5*128
    float* w5s  = bias + 5 * DH;   // 384
    float* dws  = w5s + DH * 3;    // 128
    const __half* act_h = reinterpret_cast<const __half*>(smem);

    const int tid  = threadIdx.x;
    const int lane = tid & 31;
    const int warp = tid >> 5;
    const int m_blk = warp & 3;
    const int n_blk = warp >> 2;
    const int p0 = blockIdx.x * TM;

    const uint32_t s_act = smem_u32(act32);
    const uint32_t s_wb0 = smem_u32(wbuf32);
    const uint32_t s_wb1 = s_wb0 + WS_BYTES;

    // group 0: act tile (128 rows x 160 B) + W0 tile (flat 34816 B)
    {
        const __half* gx = g_xh + (size_t)p0 * XPAD_H;
        for (int i = tid; i < 128 * 10; i += MLP_THREADS) {
            int row = i / 10, ch = i - row * 10;
            cp16(s_act + (uint32_t)(row * (ACT_W * 2) + ch * 16),
                 gx + (size_t)row * XPAD_H + ch * 8);
        }
        const __half* gw = g_wpadh;
        for (int i = tid; i < WS_BYTES / 16; i += MLP_THREADS)
            cp16(s_wb0 + (uint32_t)i * 16, gw + i * 8);
    }
    CP_COMMIT();
    // group 1: W1
    {
        const __half* gw = g_wpadh + (size_t)1 * 128 * WS_W;
        for (int i = tid; i < WS_BYTES / 16; i += MLP_THREADS)
            cp16(s_wb1 + (uint32_t)i * 16, gw + i * 8);
    }
    CP_COMMIT();

    if (tid < DH) {
        bias[0 * DH + tid] = b0[tid];
        bias[1 * DH + tid] = b1[tid];
        bias[2 * DH + tid] = b2[tid];
        bias[3 * DH + tid] = b3[tid];
        bias[4 * DH + tid] = b4[tid];
        dws[tid] = dw[tid];
    }
    for (int i = tid; i < DH * 3; i += MLP_THREADS) w5s[i] = w5[i];

    float acc[2][4][4];

#pragma unroll 1
    for (int l = 0; l < 5; l++) {
        if (l < 4) { CP_WAIT(1); } else { CP_WAIT(0); }
        __syncthreads();

        if (l == 1 && tid < TM) {
            // sigma head from pf (fp16 act)
            float sacc = db[0];
#pragma unroll 4
            for (int kk = 0; kk < DH; kk++) {
                int k = (kk + lane) & (DH - 1);
                sacc = fmaf(__half2float(act_h[tid * ACT_W + k]), dws[k], sacc);
            }
            out[(size_t)(p0 + tid) * 4 + 3] = fmaxf(sacc, 0.f);
        }

        const uint32_t* ws32 = wbuf32 + (l & 1) * (WS_BYTES / 4);
        if (l == 0) mma_gemm<5>(act32, ws32, acc, lane, m_blk, n_blk);
        else        mma_gemm<8>(act32, ws32, acc, lane, m_blk, n_blk);
        __syncthreads();

        if (l + 2 <= 4) {
            const __half* gw = g_wpadh + (size_t)(l + 2) * 128 * WS_W;
            uint32_t dst = (l & 1) ? s_wb1 : s_wb0;
            for (int i = tid; i < WS_BYTES / 16; i += MLP_THREADS)
                cp16(dst + (uint32_t)i * 16, gw + i * 8);
        }
        CP_COMMIT();

        epilogue(act32, bias + l * DH, acc, lane, m_blk, n_blk, l > 0);
    }
    __syncthreads();

    // rgb head
    if (tid < TM) {
        float r0 = b5[0], r1 = b5[1], r2 = b5[2];
#pragma unroll 4
        for (int kk = 0; kk < DH; kk++) {
            int k = (kk + lane) & (DH - 1);
            float hv = __half2float(act_h[tid * ACT_W + k]);
            r0 = fmaf(hv, w5s[k * 3 + 0], r0);
            r1 = fmaf(hv, w5s[k * 3 + 1], r1);
            r2 = fmaf(hv, w5s[k * 3 + 2], r2);
        }
        size_t o = (size_t)(p0 + tid) * 4;
        out[o + 0] = tanhf(r0);
        out[o + 1] = tanhf(r1);
        out[o + 2] = tanhf(r2);
    }
}

// ---------------------------------------------------------------------------
// Launch
// ---------------------------------------------------------------------------
extern "C" void kernel_launch(void* const* d_in, const int* in_sizes, int n_in,
                              void* d_out, int out_size) {
    const float* xyz       = (const float*)d_in[0];
    const float* src_imgs  = (const float*)d_in[2];
    const float* src_cams  = (const float*)d_in[3];
    const float* src_feats = (const float*)d_in[4];
    const float* w0 = (const float*)d_in[5];
    const float* b0 = (const float*)d_in[6];
    const float* w1 = (const float*)d_in[7];
    const float* b1 = (const float*)d_in[8];
    const float* w2 = (const float*)d_in[9];
    const float* b2 = (const float*)d_in[10];
    const float* w3 = (const float*)d_in[11];
    const float* b3 = (const float*)d_in[12];
    const float* w4 = (const float*)d_in[13];
    const float* b4 = (const float*)d_in[14];
    const float* w5 = (const float*)d_in[15];
    const float* b5 = (const float*)d_in[16];
    const float* dw = (const float*)d_in[17];
    const float* db = (const float*)d_in[18];
    float* out = (float*)d_out;

    const int smem_bytes = ACT_BYTES + 2 * WS_BYTES
                         + (5 * DH + DH * 3 + DH) * (int)sizeof(float);
    cudaFuncSetAttribute(mlp_mma_kernel,
                         cudaFuncAttributeMaxDynamicSharedMemorySize, smem_bytes);

    proj_kernel<<<1, 32>>>(src_cams);
    wprep_kernel<<<(5 * 128 * WS_W + 255) / 256, 256>>>(w0, w1, w2, w3, w4);
    tfeat_kernel<<<(B_ * NV * H1_ * W1_ * D_) / 256, 256>>>(src_feats);
    timg_kernel<<<(B_ * NV * H_ * W_ * 3 + 255) / 256, 256>>>(src_imgs);
    featurize_kernel<<<(PT * 4) / 256, 256>>>(xyz);
    mlp_mma_kernel<<<PT / TM, MLP_THREADS, smem_bytes>>>(b0, b1, b2, b3, b4,
                                                         w5, b5, dw, db, out);
}